// round 13
// baseline (speedup 1.0000x reference)
#include <cuda_runtime.h>
#include <cuda_bf16.h>
#include <math.h>
#include <stdint.h>

#define N_NODES 20000
#define N_EDGES 320000
#define H 256
#define GH 512
#define TH 768
#define NT 3

#define OFF_GEMB   5120000
#define OFF_NLOGP  5120512
#define OFF_HVINIT 5120516
#define OFF_EDGE   5120772
#define OFF_DEST   5120773

// ------------------------- scratch -------------------------
__device__ __align__(16) float g_G1[N_NODES * 1536];
__device__ __align__(16) float g_V[N_NODES * TH];
__device__ __align__(16) float g_hv1[N_NODES * H];
__device__ __align__(16) float g_cb[2 * TH];
__device__ __align__(16) float g_cw[2 * TH];
__device__ int   g_deg[N_NODES];
__device__ float g_sumhe[N_NODES];
__device__ int   g_rowptr[N_NODES + 1];
__device__ int   g_cursor[N_NODES];
__device__ int   g_csrsrc[N_EDGES];
__device__ float g_accv[NT * H];
__device__ float g_gsum[NT];
__device__ float g_scores[N_NODES];
__device__ float g_red[4];

__device__ __align__(16) __nv_bfloat16 g_hvb_hi[N_NODES * H];
__device__ __align__(16) __nv_bfloat16 g_hvb_lo[N_NODES * H];
__device__ __align__(16) __nv_bfloat16 g_Tb_hi[N_NODES * H];
__device__ __align__(16) __nv_bfloat16 g_Tb_lo[N_NODES * H];
__device__ __align__(16) __nv_bfloat16 g_Wih_hi[2 * TH * GH];
__device__ __align__(16) __nv_bfloat16 g_Wih_lo[2 * TH * GH];
__device__ __align__(16) __nv_bfloat16 g_ms_hi[2 * GH * GH];
__device__ __align__(16) __nv_bfloat16 g_ms_lo[2 * GH * GH];
__device__ __align__(16) __nv_bfloat16 g_B1_hi[2 * 1536 * H];
__device__ __align__(16) __nv_bfloat16 g_B1_lo[2 * 1536 * H];
__device__ __align__(16) __nv_bfloat16 g_B2_hi[2 * TH * H];
__device__ __align__(16) __nv_bfloat16 g_B2_lo[2 * TH * H];

__device__ __forceinline__ float warp_sum(float v) {
#pragma unroll
    for (int o = 16; o; o >>= 1) v += __shfl_xor_sync(0xffffffffu, v, o);
    return v;
}

__device__ __forceinline__ uint32_t smem_u32(const void* p) {
    uint32_t a;
    asm("{ .reg .u64 t; cvta.to.shared.u64 t, %1; cvt.u32.u64 %0, t; }" : "=r"(a) : "l"(p));
    return a;
}

// ------------------------- tensor macros -------------------------
#define CP_ASYNC(dst, src, sz) \
    asm volatile("cp.async.ca.shared.global [%0], [%1], 16, %2;" \
                 :: "r"(dst), "l"(src), "r"(sz) : "memory")
#define CP_COMMIT()  asm volatile("cp.async.commit_group;" ::: "memory")
#define CP_WAIT0()   asm volatile("cp.async.wait_group 0;" ::: "memory")

#define LDSM4(r, a) \
    asm volatile("ldmatrix.sync.aligned.m8n8.x4.shared.b16 {%0,%1,%2,%3}, [%4];" \
                 : "=r"((r)[0]), "=r"((r)[1]), "=r"((r)[2]), "=r"((r)[3]) : "r"(a))
#define LDSM2(r, a) \
    asm volatile("ldmatrix.sync.aligned.m8n8.x2.shared.b16 {%0,%1}, [%2];" \
                 : "=r"((r)[0]), "=r"((r)[1]) : "r"(a))
#define MMA_BF16(c, a, b) \
    asm volatile("mma.sync.aligned.m16n8k16.row.col.f32.bf16.bf16.f32 " \
                 "{%0,%1,%2,%3}, {%4,%5,%6,%7}, {%8,%9}, {%0,%1,%2,%3};" \
                 : "+f"((c)[0]), "+f"((c)[1]), "+f"((c)[2]), "+f"((c)[3]) \
                 : "r"((a)[0]), "r"((a)[1]), "r"((a)[2]), "r"((a)[3]), \
                   "r"((b)[0]), "r"((b)[1]))

// ------------------------- bf16 split (hv0 only) -------------------------
__global__ void split_kernel(const float* __restrict__ in,
                             __nv_bfloat16* __restrict__ hi,
                             __nv_bfloat16* __restrict__ lo, int n) {
    int i = blockIdx.x * blockDim.x + threadIdx.x;
    if (i < n) {
        float x = in[i];
        __nv_bfloat16 h = __float2bfloat16(x);
        float r = x - __bfloat162float(h);
        hi[i] = h;
        lo[i] = __float2bfloat16(r);
    }
}

// merged weight-split prep (one launch)
__global__ void prep_split_kernel(const float* __restrict__ msg_w,
                                  const float* __restrict__ w_ih,
                                  const float* __restrict__ w_hh) {
    const int nMS = GH * GH, nWI = TH * GH, nWH = TH * H;
    int i = blockIdx.x * blockDim.x + threadIdx.x;
    float x;
    __nv_bfloat16 *dh, *dl;
    if (i < 2 * nMS) {
        int t = i / nMS, k = i % nMS;
        x = msg_w[(size_t)t * (2 * H + 1) * GH + k];
        dh = g_ms_hi + i; dl = g_ms_lo + i;
    } else if (i < 2 * nMS + 2 * nWI) {
        int j = i - 2 * nMS;
        x = w_ih[j];
        dh = g_Wih_hi + j; dl = g_Wih_lo + j;
    } else if (i < 2 * nMS + 2 * nWI + 2 * nWH) {
        int j = i - 2 * nMS - 2 * nWI;
        int t = j / nWH, k = j % nWH;
        x = w_hh[j];
        size_t off = (size_t)t * 1536 * H + (size_t)TH * H + k;
        dh = g_B1_hi + off; dl = g_B1_lo + off;
    } else return;
    __nv_bfloat16 h = __float2bfloat16(x);
    *dh = h;
    *dl = __float2bfloat16(x - __bfloat162float(h));
}

// ------------------------- mma.sync bf16x3 GEMM core -------------------------
#define GEMM_SMEM 81920

template <bool BF16OUT>
__device__ __forceinline__ void gemm_core(
    const __nv_bfloat16* __restrict__ Ahi, const __nv_bfloat16* __restrict__ Alo,
    const __nv_bfloat16* __restrict__ Bhi, const __nv_bfloat16* __restrict__ Blo,
    float* __restrict__ C, __nv_bfloat16* __restrict__ Dhi, __nv_bfloat16* __restrict__ Dlo,
    int M, int Np, int K, int bm, int bn, char* smem)
{
    const int tid = threadIdx.x;
    const int wid = tid >> 5, lane = tid & 31;
    const int wm = wid & 1, wn = wid >> 1;
    const uint32_t sbase = smem_u32(smem);

    float acc[4][4][4];
#pragma unroll
    for (int i = 0; i < 4; i++)
#pragma unroll
        for (int j = 0; j < 4; j++) {
            acc[i][j][0] = 0.f; acc[i][j][1] = 0.f;
            acc[i][j][2] = 0.f; acc[i][j][3] = 0.f;
        }

    const int nch = K / 32;

    auto load_stage = [&](int s, int k0) {
        uint32_t st = sbase + s * 40960;
#pragma unroll
        for (int it = 0; it < 2; it++) {
            int u = tid + it * 256;
            int row = u >> 2, g = u & 3;
            uint32_t d = st + row * 80 + g * 16;
            int gr = bm + row;
            size_t aoff = (size_t)(gr < M ? gr : 0) * K + k0 + g * 8;
            uint32_t asz = (gr < M) ? 16u : 0u;
            CP_ASYNC(d,         Ahi + aoff, asz);
            CP_ASYNC(d + 10240, Alo + aoff, asz);
            size_t boff = (size_t)(bn + row) * K + k0 + g * 8;
            CP_ASYNC(d + 20480, Bhi + boff, 16u);
            CP_ASYNC(d + 30720, Blo + boff, 16u);
        }
    };

    load_stage(0, 0);
    CP_COMMIT();

    for (int c = 0; c < nch; c++) {
        CP_WAIT0();
        __syncthreads();
        if (c + 1 < nch) { load_stage((c + 1) & 1, (c + 1) * 32); CP_COMMIT(); }

        uint32_t st = sbase + (c & 1) * 40960;
#pragma unroll
        for (int ks = 0; ks < 2; ks++) {
            uint32_t ah[4][4], al[4][4], bh[4][2], bl[4][2];
#pragma unroll
            for (int mt = 0; mt < 4; mt++) {
                uint32_t addr = st + (uint32_t)(wm * 64 + mt * 16 + (lane & 15)) * 80
                              + ((lane >> 4) * 16) + ks * 32;
                LDSM4(ah[mt], addr);
                LDSM4(al[mt], addr + 10240);
            }
#pragma unroll
            for (int nt = 0; nt < 4; nt++) {
                uint32_t addr = st + 20480 + (uint32_t)(wn * 32 + nt * 8 + (lane & 7)) * 80
                              + (((lane >> 3) & 1) * 16) + ks * 32;
                LDSM2(bh[nt], addr);
                LDSM2(bl[nt], addr + 10240);
            }
#pragma unroll
            for (int mt = 0; mt < 4; mt++)
#pragma unroll
                for (int nt = 0; nt < 4; nt++) {
                    MMA_BF16(acc[mt][nt], ah[mt], bh[nt]);
                    MMA_BF16(acc[mt][nt], al[mt], bh[nt]);
                    MMA_BF16(acc[mt][nt], ah[mt], bl[nt]);
                }
        }
    }

#pragma unroll
    for (int mt = 0; mt < 4; mt++) {
        int r0 = bm + wm * 64 + mt * 16 + (lane >> 2);
#pragma unroll
        for (int nt = 0; nt < 4; nt++) {
            int col = bn + wn * 32 + nt * 8 + (lane & 3) * 2;
            if (BF16OUT) {
#pragma unroll
                for (int hh = 0; hh < 2; hh++) {
                    int r = r0 + hh * 8;
                    if (r < M) {
                        float vx = acc[mt][nt][hh * 2], vy = acc[mt][nt][hh * 2 + 1];
                        __nv_bfloat16 hx = __float2bfloat16(vx);
                        __nv_bfloat16 hy = __float2bfloat16(vy);
                        __nv_bfloat16 lx = __float2bfloat16(vx - __bfloat162float(hx));
                        __nv_bfloat16 ly = __float2bfloat16(vy - __bfloat162float(hy));
                        size_t o = (size_t)r * Np + col;
                        *reinterpret_cast<__nv_bfloat162*>(Dhi + o) = __nv_bfloat162(hx, hy);
                        *reinterpret_cast<__nv_bfloat162*>(Dlo + o) = __nv_bfloat162(lx, ly);
                    }
                }
            } else {
                if (r0 < M) {
                    float2 v; v.x = acc[mt][nt][0]; v.y = acc[mt][nt][1];
                    *reinterpret_cast<float2*>(C + (size_t)r0 * Np + col) = v;
                }
                if (r0 + 8 < M) {
                    float2 v; v.x = acc[mt][nt][2]; v.y = acc[mt][nt][3];
                    *reinterpret_cast<float2*>(C + (size_t)(r0 + 8) * Np + col) = v;
                }
            }
        }
    }
}

// per-round GEMM with z offset: z<12 -> G1 tile, z>=12 -> V tile
__global__ void __launch_bounds__(256) mma_gemm_dual_kernel(
    const __nv_bfloat16* __restrict__ hvhi, const __nv_bfloat16* __restrict__ hvlo,
    const __nv_bfloat16* __restrict__ thi,  const __nv_bfloat16* __restrict__ tlo,
    const __nv_bfloat16* __restrict__ b1hi, const __nv_bfloat16* __restrict__ b1lo,
    const __nv_bfloat16* __restrict__ b2hi, const __nv_bfloat16* __restrict__ b2lo,
    float* __restrict__ G1, float* __restrict__ V, int z0)
{
    extern __shared__ __align__(128) char smem[];
    int z = z0 + blockIdx.x;
    int bm = blockIdx.y * 128;
    if (z < 12)
        gemm_core<false>(hvhi, hvlo, b1hi, b1lo, G1, nullptr, nullptr,
                         N_NODES, 1536, H, bm, z * 128, smem);
    else
        gemm_core<false>(thi, tlo, b2hi, b2lo, V, nullptr, nullptr,
                         N_NODES, TH, H, bm, (z - 12) * 128, smem);
}

// batched small GEMM with bf16 hi/lo epilogue
__global__ void __launch_bounds__(256) mma_gemm_batch_kernel() {
    extern __shared__ __align__(128) char smem[];
    int z = blockIdx.z;
    int t = z >> 1, half = z & 1;
    __nv_bfloat16* Dhi = half ? (g_B2_hi + (size_t)t * TH * H)
                              : (g_B1_hi + (size_t)t * 1536 * H);
    __nv_bfloat16* Dlo = half ? (g_B2_lo + (size_t)t * TH * H)
                              : (g_B1_lo + (size_t)t * 1536 * H);
    gemm_core<true>(g_Wih_hi + (size_t)t * TH * GH, g_Wih_lo + (size_t)t * TH * GH,
                    g_ms_hi + (size_t)t * GH * GH + (size_t)half * H * GH,
                    g_ms_lo + (size_t)t * GH * GH + (size_t)half * H * GH,
                    nullptr, Dhi, Dlo, TH, H, GH,
                    blockIdx.y * 128, blockIdx.x * 128, smem);
}

// ------------------------- cb/cw precompute -------------------------
__global__ void cbcw_kernel(const float* __restrict__ msg_w, const float* __restrict__ msg_b,
                            const float* __restrict__ w_ih) {
    int g = blockIdx.x * 8 + (threadIdx.x >> 5);
    if (g >= 2 * TH) return;
    int t = g / TH, j = g % TH, lane = threadIdx.x & 31;
    const float* wr = w_ih + ((size_t)t * TH + j) * GH;
    const float* mb = msg_b + t * GH;
    const float* wh = msg_w + (size_t)t * (2 * H + 1) * GH + (size_t)(2 * H) * GH;
    float s1 = 0.f, s2 = 0.f;
    for (int c = lane; c < GH; c += 32) {
        float w = wr[c];
        s1 += mb[c] * w;
        s2 += wh[c] * w;
    }
    s1 = warp_sum(s1); s2 = warp_sum(s2);
    if (lane == 0) { g_cb[g] = s1; g_cw[g] = s2; }
}

// ------------------------- init / CSR build -------------------------
__global__ void init_kernel() {
    int i = blockIdx.x * blockDim.x + threadIdx.x;
    if (i < N_NODES) { g_deg[i] = 0; g_sumhe[i] = 0.f; g_cursor[i] = 0; }
    if (i < NT * H) g_accv[i] = 0.f;
    if (i < NT) g_gsum[i] = 0.f;
}

__global__ void deg_kernel(const int* __restrict__ dst, const float* __restrict__ he) {
    int e = blockIdx.x * blockDim.x + threadIdx.x;
    if (e < N_EDGES) {
        atomicAdd(&g_deg[dst[e]], 1);
        atomicAdd(&g_sumhe[dst[e]], he[e]);
    }
}

__global__ void scan_kernel() {
    __shared__ int s[1024];
    __shared__ int carry;
    if (threadIdx.x == 0) { carry = 0; g_rowptr[0] = 0; }
    __syncthreads();
    for (int base = 0; base < N_NODES; base += 8192) {
        int idx0 = base + threadIdx.x * 8;
        int v[8]; int sum = 0;
#pragma unroll
        for (int i = 0; i < 8; i++) {
            int ii = idx0 + i;
            v[i] = (ii < N_NODES) ? g_deg[ii] : 0;
            sum += v[i];
        }
        s[threadIdx.x] = sum;
        __syncthreads();
        for (int d = 1; d < 1024; d <<= 1) {
            int t = (threadIdx.x >= d) ? s[threadIdx.x - d] : 0;
            __syncthreads();
            s[threadIdx.x] += t;
            __syncthreads();
        }
        int run = s[threadIdx.x] - sum + carry;
#pragma unroll
        for (int i = 0; i < 8; i++) {
            int ii = idx0 + i;
            run += v[i];
            if (ii < N_NODES) g_rowptr[ii + 1] = run;
        }
        __syncthreads();
        if (threadIdx.x == 1023) carry += s[1023];
        __syncthreads();
    }
}

__global__ void scatter_kernel(const int* __restrict__ src, const int* __restrict__ dst) {
    int e = blockIdx.x * blockDim.x + threadIdx.x;
    if (e < N_EDGES) {
        int d = dst[e];
        int slot = atomicAdd(&g_cursor[d], 1);
        g_csrsrc[g_rowptr[d] + slot] = src[e];
    }
}

// ------------------------- T aggregation + fused bf16 split -------------------------
__global__ void taggr_kernel(const float* __restrict__ hv) {
    int v = blockIdx.x;
    int c = threadIdx.x * 4;   // 64 threads
    int beg = g_rowptr[v], end = g_rowptr[v + 1];
    float ax = 0.f, ay = 0.f, az = 0.f, aw = 0.f;
    int p = beg;
    for (; p + 1 < end; p += 2) {
        int s0 = g_csrsrc[p], s1 = g_csrsrc[p + 1];
        float4 v0 = *reinterpret_cast<const float4*>(hv + (size_t)s0 * H + c);
        float4 v1 = *reinterpret_cast<const float4*>(hv + (size_t)s1 * H + c);
        ax += v0.x + v1.x; ay += v0.y + v1.y; az += v0.z + v1.z; aw += v0.w + v1.w;
    }
    if (p < end) {
        int s0 = g_csrsrc[p];
        float4 v0 = *reinterpret_cast<const float4*>(hv + (size_t)s0 * H + c);
        ax += v0.x; ay += v0.y; az += v0.z; aw += v0.w;
    }
    __nv_bfloat16 hx = __float2bfloat16(ax), hy = __float2bfloat16(ay);
    __nv_bfloat16 hz = __float2bfloat16(az), hw = __float2bfloat16(aw);
    __nv_bfloat16 lx = __float2bfloat16(ax - __bfloat162float(hx));
    __nv_bfloat16 ly = __float2bfloat16(ay - __bfloat162float(hy));
    __nv_bfloat16 lz = __float2bfloat16(az - __bfloat162float(hz));
    __nv_bfloat16 lw = __float2bfloat16(aw - __bfloat162float(hw));
    size_t off = (size_t)v * H + c;
    *reinterpret_cast<__nv_bfloat162*>(&g_Tb_hi[off])     = __nv_bfloat162(hx, hy);
    *reinterpret_cast<__nv_bfloat162*>(&g_Tb_hi[off + 2]) = __nv_bfloat162(hz, hw);
    *reinterpret_cast<__nv_bfloat162*>(&g_Tb_lo[off])     = __nv_bfloat162(lx, ly);
    *reinterpret_cast<__nv_bfloat162*>(&g_Tb_lo[off + 2]) = __nv_bfloat162(lz, lw);
}

// ------------------------- fused GRU (+ optional dest-score dot) -------------------------
template <bool WRITE_SPLIT, bool SCORE>
__global__ void gru2_kernel(const float* __restrict__ hv_in, float* __restrict__ hv_out,
                            const float* __restrict__ cb, const float* __restrict__ cw,
                            const float* __restrict__ b_ih, const float* __restrict__ b_hh,
                            const float* __restrict__ dw) {
    __shared__ float spart[8];
    int idx = blockIdx.x * blockDim.x + threadIdx.x;
    if (idx >= N_NODES * (H / 4)) return;
    int n = idx / (H / 4);
    int c = (idx % (H / 4)) * 4;
    float deg = (float)(g_rowptr[n + 1] - g_rowptr[n]);
    float sh = g_sumhe[n];
    const float* G1 = g_G1 + (size_t)n * 1536;
    const float* V = g_V + (size_t)n * TH;
#define LD4(p) (*reinterpret_cast<const float4*>(p))
    float4 Ur = LD4(G1 + c),        Uz = LD4(G1 + 256 + c),  Un = LD4(G1 + 512 + c);
    float4 Hr = LD4(G1 + 768 + c),  Hz = LD4(G1 + 1024 + c), Hn = LD4(G1 + 1280 + c);
    float4 Vr = LD4(V + c),         Vz = LD4(V + 256 + c),   Vn = LD4(V + 512 + c);
    float4 cbr = LD4(cb + c), cbz = LD4(cb + 256 + c), cbn = LD4(cb + 512 + c);
    float4 cwr = LD4(cw + c), cwz = LD4(cw + 256 + c), cwn = LD4(cw + 512 + c);
    float4 bir = LD4(b_ih + c), biz = LD4(b_ih + 256 + c), bin_ = LD4(b_ih + 512 + c);
    float4 bhr = LD4(b_hh + c), bhz = LD4(b_hh + 256 + c), bhn = LD4(b_hh + 512 + c);
    float4 hc = LD4(hv_in + (size_t)n * H + c);
#undef LD4
    float4 o;
#define GRU1(X) { \
    float gir = deg * (Ur.X + cbr.X) + Vr.X + sh * cwr.X + bir.X; \
    float giz = deg * (Uz.X + cbz.X) + Vz.X + sh * cwz.X + biz.X; \
    float gin = deg * (Un.X + cbn.X) + Vn.X + sh * cwn.X + bin_.X; \
    float rr = 1.f / (1.f + expf(-(gir + Hr.X + bhr.X))); \
    float zz = 1.f / (1.f + expf(-(giz + Hz.X + bhz.X))); \
    float nn = tanhf(gin + rr * (Hn.X + bhn.X)); \
    o.X = (1.f - zz) * nn + zz * hc.X; }
    GRU1(x) GRU1(y) GRU1(z) GRU1(w)
#undef GRU1
    *reinterpret_cast<float4*>(hv_out + (size_t)n * H + c) = o;
    if (WRITE_SPLIT) {
        __nv_bfloat16 hx = __float2bfloat16(o.x), hy = __float2bfloat16(o.y);
        __nv_bfloat16 hz_ = __float2bfloat16(o.z), hw = __float2bfloat16(o.w);
        __nv_bfloat16 lx = __float2bfloat16(o.x - __bfloat162float(hx));
        __nv_bfloat16 ly = __float2bfloat16(o.y - __bfloat162float(hy));
        __nv_bfloat16 lz = __float2bfloat16(o.z - __bfloat162float(hz_));
        __nv_bfloat16 lw = __float2bfloat16(o.w - __bfloat162float(hw));
        size_t boff = (size_t)n * H + c;
        *reinterpret_cast<__nv_bfloat162*>(&g_hvb_hi[boff])     = __nv_bfloat162(hx, hy);
        *reinterpret_cast<__nv_bfloat162*>(&g_hvb_hi[boff + 2]) = __nv_bfloat162(hz_, hw);
        *reinterpret_cast<__nv_bfloat162*>(&g_hvb_lo[boff])     = __nv_bfloat162(lx, ly);
        *reinterpret_cast<__nv_bfloat162*>(&g_hvb_lo[boff + 2]) = __nv_bfloat162(lz, lw);
    }
    if (SCORE) {
        // dest score raw dot: hv_out[n] . dw[0:256]; cst term cancels in log_softmax
        float s = o.x * dw[c] + o.y * dw[c + 1] + o.z * dw[c + 2] + o.w * dw[c + 3];
        s = warp_sum(s);
        int wid = threadIdx.x >> 5;
        if ((threadIdx.x & 31) == 0) spart[wid] = s;
        __syncthreads();
        if ((threadIdx.x & 63) == 0 && n < N_NODES - 1)
            g_scores[n] = spart[wid] + spart[wid + 1];
    }
}

// ------------------------- graph embed -------------------------
__global__ void gate_kernel(const float* __restrict__ hv, const int* __restrict__ ntype,
                            const float* __restrict__ gate_w, const float* __restrict__ gate_b) {
    __shared__ float sacc[NT * H];
    __shared__ float ssum[NT];
    int tid = threadIdx.x;
    for (int i = tid; i < NT * H; i += 256) sacc[i] = 0.f;
    if (tid < NT) ssum[tid] = 0.f;
    __syncthreads();
    int warp = tid >> 5, lane = tid & 31;
    int n = blockIdx.x * 8 + warp;
    if (n < N_NODES) {
        int t = ntype[n];
        const float* hrow = hv + (size_t)n * H;
        const float* gw = gate_w + t * H;
        float dot = 0.f;
        for (int k = lane; k < H; k += 32) dot += hrow[k] * gw[k];
        dot = warp_sum(dot);
        dot = __shfl_sync(0xffffffffu, dot, 0);
        float g = 1.f / (1.f + expf(-(dot + gate_b[t])));
        for (int k = lane; k < H; k += 32) atomicAdd(&sacc[t * H + k], g * hrow[k]);
        if (lane == 0) atomicAdd(&ssum[t], g);
    }
    __syncthreads();
    for (int i = tid; i < NT * H; i += 256) if (sacc[i] != 0.f) atomicAdd(&g_accv[i], sacc[i]);
    if (tid < NT) atomicAdd(&g_gsum[tid], ssum[tid]);
}

__global__ void gembed_kernel(const float* __restrict__ tog_w, const float* __restrict__ tog_b,
                              float* __restrict__ outg) {
    int c = blockIdx.x * 128 + threadIdx.x;
    float acc = 0.f;
#pragma unroll
    for (int t = 0; t < NT; t++) {
        acc += g_gsum[t] * tog_b[t * GH + c];
        const float* W = tog_w + (size_t)t * H * GH;
        const float* av = g_accv + t * H;
#pragma unroll 4
        for (int k = 0; k < H; k++) acc += av[k] * W[(size_t)k * GH + c];
    }
    outg[c] = acc;
}

// ------------------------- merged tail heads -------------------------
__global__ void heads_kernel(const float* __restrict__ ge, const float* __restrict__ hv,
                             const float* __restrict__ addn_w, const float* __restrict__ addn_b,
                             const float* __restrict__ nte, const float* __restrict__ init_w,
                             const float* __restrict__ init_b,
                             const float* __restrict__ adde_w, const float* __restrict__ adde_b,
                             float* __restrict__ out) {
    int tid = threadIdx.x;
    if (blockIdx.x == 0) {
        __shared__ float logits[4];
        if (tid < 128) {
            int t = tid >> 5, lane = tid & 31;
            float dot = 0.f;
            for (int k = lane; k < GH; k += 32) dot += ge[k] * addn_w[k * 4 + t];
            dot = warp_sum(dot);
            if (lane == 0) logits[t] = dot + addn_b[t];
        }
        __syncthreads();
        if (tid == 0) {
            float m = fmaxf(fmaxf(logits[0], logits[1]), fmaxf(logits[2], logits[3]));
            float s = 0.f;
            for (int i = 0; i < 4; i++) s += expf(logits[i] - m);
            float l = logf(s);
            for (int i = 0; i < 4; i++) out[OFF_NLOGP + i] = logits[i] - m - l;
        }
    } else if (blockIdx.x == 1) {
        int c = tid;
        float a0 = init_b[c], a1 = 0.f, a2 = 0.f, a3 = 0.f;
#pragma unroll 4
        for (int k = 0; k < H; k += 4) {
            a0 += nte[k] * init_w[(size_t)k * H + c];
            a1 += nte[k + 1] * init_w[(size_t)(k + 1) * H + c];
            a2 += nte[k + 2] * init_w[(size_t)(k + 2) * H + c];
            a3 += nte[k + 3] * init_w[(size_t)(k + 3) * H + c];
        }
#pragma unroll 4
        for (int k = 0; k < GH; k += 4) {
            a0 += ge[k] * init_w[(size_t)(H + k) * H + c];
            a1 += ge[k + 1] * init_w[(size_t)(H + k + 1) * H + c];
            a2 += ge[k + 2] * init_w[(size_t)(H + k + 2) * H + c];
            a3 += ge[k + 3] * init_w[(size_t)(H + k + 3) * H + c];
        }
        out[OFF_HVINIT + c] = a0 + a1 + a2 + a3;
    } else {
        if (tid < 32) {
            const float* se = hv + (size_t)(N_NODES - 1) * H;
            float dot = 0.f;
            for (int k = tid; k < GH; k += 32) dot += ge[k] * adde_w[k];
            for (int k = tid; k < H; k += 32) dot += se[k] * adde_w[GH + k];
            dot = warp_sum(dot);
            if (tid == 0) out[OFF_EDGE] = dot + adde_b[0];
        }
    }
}

// ------------------------- dest logsoftmax (cst cancels) -------------------------
__global__ void destreduce_kernel() {
    __shared__ float s[1024];
    int tid = threadIdx.x;
    float m = -INFINITY;
    for (int i = tid; i < N_NODES - 1; i += 1024) m = fmaxf(m, g_scores[i]);
    s[tid] = m; __syncthreads();
    for (int d = 512; d; d >>= 1) {
        if (tid < d) s[tid] = fmaxf(s[tid], s[tid + d]);
        __syncthreads();
    }
    float M = s[0];
    __syncthreads();
    float sum = 0.f;
    for (int i = tid; i < N_NODES - 1; i += 1024) sum += expf(g_scores[i] - M);
    s[tid] = sum; __syncthreads();
    for (int d = 512; d; d >>= 1) {
        if (tid < d) s[tid] += s[tid + d];
        __syncthreads();
    }
    if (tid == 0) { g_red[0] = M; g_red[1] = logf(s[0]); }
}

__global__ void destwrite_kernel(float* __restrict__ out) {
    int i = blockIdx.x * blockDim.x + threadIdx.x;
    if (i < N_NODES - 1) out[i] = g_scores[i] - g_red[0] - g_red[1];
}

// ------------------------- host -------------------------
extern "C" void kernel_launch(void* const* d_in, const int* in_sizes, int n_in,
                              void* d_out, int out_size) {
    const float* hv0   = (const float*)d_in[0];
    const float* he    = (const float*)d_in[1];
    const int*   ntype = (const int*)d_in[2];
    const int*   src   = (const int*)d_in[3];
    const int*   dst   = (const int*)d_in[4];
    const float* msg_w = (const float*)d_in[5];
    const float* msg_b = (const float*)d_in[6];
    const float* w_ih  = (const float*)d_in[7];
    const float* b_ih  = (const float*)d_in[8];
    const float* w_hh  = (const float*)d_in[9];
    const float* b_hh  = (const float*)d_in[10];
    const float* gate_w = (const float*)d_in[11];
    const float* gate_b = (const float*)d_in[12];
    const float* tog_w  = (const float*)d_in[13];
    const float* tog_b  = (const float*)d_in[14];
    const float* addn_w = (const float*)d_in[15];
    const float* addn_b = (const float*)d_in[16];
    const float* nte    = (const float*)d_in[17];
    const float* init_w = (const float*)d_in[18];
    const float* init_b = (const float*)d_in[19];
    const float* adde_w = (const float*)d_in[20];
    const float* adde_b = (const float*)d_in[21];
    const float* dest_w = (const float*)d_in[22];
    const float* dest_b = (const float*)d_in[23];
    float* out = (float*)d_out;

    void *p;
    cudaGetSymbolAddress(&p, g_G1);      float* G1 = (float*)p;
    cudaGetSymbolAddress(&p, g_V);       float* V = (float*)p;
    cudaGetSymbolAddress(&p, g_hv1);     float* Hv1 = (float*)p;
    cudaGetSymbolAddress(&p, g_cb);      float* Cb = (float*)p;
    cudaGetSymbolAddress(&p, g_cw);      float* Cw = (float*)p;
    cudaGetSymbolAddress(&p, g_hvb_hi);  __nv_bfloat16* HvHi = (__nv_bfloat16*)p;
    cudaGetSymbolAddress(&p, g_hvb_lo);  __nv_bfloat16* HvLo = (__nv_bfloat16*)p;
    cudaGetSymbolAddress(&p, g_Tb_hi);   __nv_bfloat16* TbHi = (__nv_bfloat16*)p;
    cudaGetSymbolAddress(&p, g_Tb_lo);   __nv_bfloat16* TbLo = (__nv_bfloat16*)p;
    cudaGetSymbolAddress(&p, g_B1_hi);   __nv_bfloat16* B1Hi = (__nv_bfloat16*)p;
    cudaGetSymbolAddress(&p, g_B1_lo);   __nv_bfloat16* B1Lo = (__nv_bfloat16*)p;
    cudaGetSymbolAddress(&p, g_B2_hi);   __nv_bfloat16* B2Hi = (__nv_bfloat16*)p;
    cudaGetSymbolAddress(&p, g_B2_lo);   __nv_bfloat16* B2Lo = (__nv_bfloat16*)p;

    // Streams/events created ONCE on the first (uncaptured) call, reused after.
    static cudaStream_t sA = nullptr, sB = nullptr;
    static cudaEvent_t evFork, evPrep, evT0, evV0, evG, evV1, evTail, evD;
    static bool s_init = false;
    if (!s_init) {
        cudaStreamCreateWithFlags(&sA, cudaStreamNonBlocking);
        cudaStreamCreateWithFlags(&sB, cudaStreamNonBlocking);
        cudaEventCreateWithFlags(&evFork, cudaEventDisableTiming);
        cudaEventCreateWithFlags(&evPrep, cudaEventDisableTiming);
        cudaEventCreateWithFlags(&evT0,   cudaEventDisableTiming);
        cudaEventCreateWithFlags(&evV0,   cudaEventDisableTiming);
        cudaEventCreateWithFlags(&evG,    cudaEventDisableTiming);
        cudaEventCreateWithFlags(&evV1,   cudaEventDisableTiming);
        cudaEventCreateWithFlags(&evTail, cudaEventDisableTiming);
        cudaEventCreateWithFlags(&evD,    cudaEventDisableTiming);
        cudaFuncSetAttribute(mma_gemm_dual_kernel,
                             cudaFuncAttributeMaxDynamicSharedMemorySize, GEMM_SMEM);
        cudaFuncSetAttribute(mma_gemm_batch_kernel,
                             cudaFuncAttributeMaxDynamicSharedMemorySize, GEMM_SMEM);
        s_init = true;
    }

    const int MT = (N_NODES + 127) / 128;  // 157

    // ---- fork prep branch onto sB: hv0 split + weight splits + batch GEMM ----
    cudaEventRecord(evFork, 0);
    cudaStreamWaitEvent(sB, evFork, 0);
    split_kernel<<<(N_NODES * H + 255) / 256, 256, 0, sB>>>(hv0, HvHi, HvLo, N_NODES * H);
    {
        const int total = 2 * (GH * GH) + 2 * (TH * GH) + 2 * (TH * H);
        prep_split_kernel<<<(total + 255) / 256, 256, 0, sB>>>(msg_w, w_ih, w_hh);
    }
    mma_gemm_batch_kernel<<<dim3(H / 128, TH / 128, 4), 256, GEMM_SMEM, sB>>>();
    cbcw_kernel<<<(2 * TH + 7) / 8, 256, 0, sB>>>(msg_w, msg_b, w_ih);
    cudaEventRecord(evPrep, sB);

    // ---- main: CSR build ----
    init_kernel<<<(N_NODES + 255) / 256, 256>>>();
    deg_kernel<<<(N_EDGES + 255) / 256, 256>>>(dst, he);
    scan_kernel<<<1, 1024>>>();
    scatter_kernel<<<(N_EDGES + 255) / 256, 256>>>(src, dst);
    cudaEventRecord(evT0, 0);

    // ---- round 0 ----
    {
        const __nv_bfloat16 *b1h = B1Hi, *b1l = B1Lo, *b2h = B2Hi, *b2l = B2Lo;
        // sA: taggr (needs CSR + raw hv0) -> V GEMM (needs prep too)
        cudaStreamWaitEvent(sA, evT0, 0);
        taggr_kernel<<<N_NODES, 64, 0, sA>>>(hv0);
        cudaStreamWaitEvent(sA, evPrep, 0);
        mma_gemm_dual_kernel<<<dim3(6, MT), 256, GEMM_SMEM, sA>>>(
            HvHi, HvLo, TbHi, TbLo, b1h, b1l, b2h, b2l, G1, V, 12);
        cudaEventRecord(evV0, sA);
        // main: G1 GEMM (needs hv split + B1 from prep)
        cudaStreamWaitEvent(0, evPrep, 0);
        mma_gemm_dual_kernel<<<dim3(12, MT), 256, GEMM_SMEM>>>(
            HvHi, HvLo, TbHi, TbLo, b1h, b1l, b2h, b2l, G1, V, 0);
        cudaStreamWaitEvent(0, evV0, 0);
        gru2_kernel<true, false><<<(N_NODES * (H / 4) + 255) / 256, 256>>>(
            hv0, Hv1, Cb, Cw, b_ih, b_hh, dest_w);
        cudaEventRecord(evG, 0);
    }

    // ---- round 1 ----
    {
        const __nv_bfloat16 *b1h = B1Hi + (size_t)1536 * H, *b1l = B1Lo + (size_t)1536 * H;
        const __nv_bfloat16 *b2h = B2Hi + (size_t)TH * H,   *b2l = B2Lo + (size_t)TH * H;
        cudaStreamWaitEvent(sA, evG, 0);
        taggr_kernel<<<N_NODES, 64, 0, sA>>>(Hv1);
        mma_gemm_dual_kernel<<<dim3(6, MT), 256, GEMM_SMEM, sA>>>(
            HvHi, HvLo, TbHi, TbLo, b1h, b1l, b2h, b2l, G1, V, 12);
        cudaEventRecord(evV1, sA);
        mma_gemm_dual_kernel<<<dim3(12, MT), 256, GEMM_SMEM>>>(
            HvHi, HvLo, TbHi, TbLo, b1h, b1l, b2h, b2l, G1, V, 0);
        cudaStreamWaitEvent(0, evV1, 0);
        gru2_kernel<false, true><<<(N_NODES * (H / 4) + 255) / 256, 256>>>(
            Hv1, out, Cb + TH, Cw + TH, b_ih + TH, b_hh + TH, dest_w);
        cudaEventRecord(evTail, 0);
    }

    // ---- tail: dest logsoftmax on sA, embed chain on main ----
    cudaStreamWaitEvent(sA, evTail, 0);
    destreduce_kernel<<<1, 1024, 0, sA>>>();
    destwrite_kernel<<<(N_NODES - 1 + 255) / 256, 256, 0, sA>>>(out + OFF_DEST);
    cudaEventRecord(evD, sA);

    gate_kernel<<<(N_NODES + 7) / 8, 256>>>(out, ntype, gate_w, gate_b);
    gembed_kernel<<<4, 128>>>(tog_w, tog_b, out + OFF_GEMB);
    heads_kernel<<<3, 256>>>(out + OFF_GEMB, out, addn_w, addn_b,
                             nte, init_w, init_b, adde_w, adde_b, out);

    // join everything back to the main stream before capture ends
    cudaStreamWaitEvent(0, evD, 0);
}

// round 14
// speedup vs baseline: 1.1038x; 1.1038x over previous
#include <cuda_runtime.h>
#include <cuda_bf16.h>
#include <math.h>
#include <stdint.h>

#define N_NODES 20000
#define N_EDGES 320000
#define H 256
#define GH 512
#define TH 768
#define NT 3

#define OFF_GEMB   5120000
#define OFF_NLOGP  5120512
#define OFF_HVINIT 5120516
#define OFF_EDGE   5120772
#define OFF_DEST   5120773

// ------------------------- scratch -------------------------
__device__ __align__(16) float g_G1[N_NODES * 1536];
__device__ __align__(16) float g_V[N_NODES * TH];
__device__ __align__(16) float g_hv1[N_NODES * H];
__device__ __align__(16) float g_cb[2 * TH];
__device__ __align__(16) float g_cw[2 * TH];
__device__ int   g_deg[N_NODES];
__device__ float g_sumhe[N_NODES];
__device__ int   g_rowptr[N_NODES + 1];
__device__ int   g_cursor[N_NODES];
__device__ int   g_csrsrc[N_EDGES];
__device__ float g_accv[NT * H];
__device__ float g_gsum[NT];
__device__ float g_gpart[NT * GH];
__device__ float g_scores[N_NODES];
__device__ float g_red[4];

__device__ __align__(16) __nv_bfloat16 g_hvb_hi[N_NODES * H];
__device__ __align__(16) __nv_bfloat16 g_hvb_lo[N_NODES * H];
__device__ __align__(16) __nv_bfloat16 g_Tb_hi[N_NODES * H];
__device__ __align__(16) __nv_bfloat16 g_Tb_lo[N_NODES * H];
__device__ __align__(16) __nv_bfloat16 g_Wih_hi[2 * TH * GH];
__device__ __align__(16) __nv_bfloat16 g_Wih_lo[2 * TH * GH];
__device__ __align__(16) __nv_bfloat16 g_ms_hi[2 * GH * GH];
__device__ __align__(16) __nv_bfloat16 g_ms_lo[2 * GH * GH];
__device__ __align__(16) __nv_bfloat16 g_B1_hi[2 * 1536 * H];
__device__ __align__(16) __nv_bfloat16 g_B1_lo[2 * 1536 * H];
__device__ __align__(16) __nv_bfloat16 g_B2_hi[2 * TH * H];
__device__ __align__(16) __nv_bfloat16 g_B2_lo[2 * TH * H];

__device__ __forceinline__ float warp_sum(float v) {
#pragma unroll
    for (int o = 16; o; o >>= 1) v += __shfl_xor_sync(0xffffffffu, v, o);
    return v;
}

__device__ __forceinline__ uint32_t smem_u32(const void* p) {
    uint32_t a;
    asm("{ .reg .u64 t; cvta.to.shared.u64 t, %1; cvt.u32.u64 %0, t; }" : "=r"(a) : "l"(p));
    return a;
}

// ------------------------- tensor macros -------------------------
#define CP_ASYNC(dst, src, sz) \
    asm volatile("cp.async.ca.shared.global [%0], [%1], 16, %2;" \
                 :: "r"(dst), "l"(src), "r"(sz) : "memory")
#define CP_COMMIT()  asm volatile("cp.async.commit_group;" ::: "memory")
#define CP_WAIT0()   asm volatile("cp.async.wait_group 0;" ::: "memory")

#define LDSM4(r, a) \
    asm volatile("ldmatrix.sync.aligned.m8n8.x4.shared.b16 {%0,%1,%2,%3}, [%4];" \
                 : "=r"((r)[0]), "=r"((r)[1]), "=r"((r)[2]), "=r"((r)[3]) : "r"(a))
#define LDSM2(r, a) \
    asm volatile("ldmatrix.sync.aligned.m8n8.x2.shared.b16 {%0,%1}, [%2];" \
                 : "=r"((r)[0]), "=r"((r)[1]) : "r"(a))
#define MMA_BF16(c, a, b) \
    asm volatile("mma.sync.aligned.m16n8k16.row.col.f32.bf16.bf16.f32 " \
                 "{%0,%1,%2,%3}, {%4,%5,%6,%7}, {%8,%9}, {%0,%1,%2,%3};" \
                 : "+f"((c)[0]), "+f"((c)[1]), "+f"((c)[2]), "+f"((c)[3]) \
                 : "r"((a)[0]), "r"((a)[1]), "r"((a)[2]), "r"((a)[3]), \
                   "r"((b)[0]), "r"((b)[1]))

// ------------------------- bf16 split (hv0 only) -------------------------
__global__ void split_kernel(const float* __restrict__ in,
                             __nv_bfloat16* __restrict__ hi,
                             __nv_bfloat16* __restrict__ lo, int n) {
    int i = blockIdx.x * blockDim.x + threadIdx.x;
    if (i < n) {
        float x = in[i];
        __nv_bfloat16 h = __float2bfloat16(x);
        float r = x - __bfloat162float(h);
        hi[i] = h;
        lo[i] = __float2bfloat16(r);
    }
}

// merged weight-split prep (one launch)
__global__ void prep_split_kernel(const float* __restrict__ msg_w,
                                  const float* __restrict__ w_ih,
                                  const float* __restrict__ w_hh) {
    const int nMS = GH * GH, nWI = TH * GH, nWH = TH * H;
    int i = blockIdx.x * blockDim.x + threadIdx.x;
    float x;
    __nv_bfloat16 *dh, *dl;
    if (i < 2 * nMS) {
        int t = i / nMS, k = i % nMS;
        x = msg_w[(size_t)t * (2 * H + 1) * GH + k];
        dh = g_ms_hi + i; dl = g_ms_lo + i;
    } else if (i < 2 * nMS + 2 * nWI) {
        int j = i - 2 * nMS;
        x = w_ih[j];
        dh = g_Wih_hi + j; dl = g_Wih_lo + j;
    } else if (i < 2 * nMS + 2 * nWI + 2 * nWH) {
        int j = i - 2 * nMS - 2 * nWI;
        int t = j / nWH, k = j % nWH;
        x = w_hh[j];
        size_t off = (size_t)t * 1536 * H + (size_t)TH * H + k;
        dh = g_B1_hi + off; dl = g_B1_lo + off;
    } else return;
    __nv_bfloat16 h = __float2bfloat16(x);
    *dh = h;
    *dl = __float2bfloat16(x - __bfloat162float(h));
}

// ------------------------- mma.sync bf16x3 GEMM core -------------------------
#define GEMM_SMEM 81920

template <bool BF16OUT>
__device__ __forceinline__ void gemm_core(
    const __nv_bfloat16* __restrict__ Ahi, const __nv_bfloat16* __restrict__ Alo,
    const __nv_bfloat16* __restrict__ Bhi, const __nv_bfloat16* __restrict__ Blo,
    float* __restrict__ C, __nv_bfloat16* __restrict__ Dhi, __nv_bfloat16* __restrict__ Dlo,
    int M, int Np, int K, int bm, int bn, char* smem)
{
    const int tid = threadIdx.x;
    const int wid = tid >> 5, lane = tid & 31;
    const int wm = wid & 1, wn = wid >> 1;
    const uint32_t sbase = smem_u32(smem);

    float acc[4][4][4];
#pragma unroll
    for (int i = 0; i < 4; i++)
#pragma unroll
        for (int j = 0; j < 4; j++) {
            acc[i][j][0] = 0.f; acc[i][j][1] = 0.f;
            acc[i][j][2] = 0.f; acc[i][j][3] = 0.f;
        }

    const int nch = K / 32;

    auto load_stage = [&](int s, int k0) {
        uint32_t st = sbase + s * 40960;
#pragma unroll
        for (int it = 0; it < 2; it++) {
            int u = tid + it * 256;
            int row = u >> 2, g = u & 3;
            uint32_t d = st + row * 80 + g * 16;
            int gr = bm + row;
            size_t aoff = (size_t)(gr < M ? gr : 0) * K + k0 + g * 8;
            uint32_t asz = (gr < M) ? 16u : 0u;
            CP_ASYNC(d,         Ahi + aoff, asz);
            CP_ASYNC(d + 10240, Alo + aoff, asz);
            size_t boff = (size_t)(bn + row) * K + k0 + g * 8;
            CP_ASYNC(d + 20480, Bhi + boff, 16u);
            CP_ASYNC(d + 30720, Blo + boff, 16u);
        }
    };

    load_stage(0, 0);
    CP_COMMIT();

    for (int c = 0; c < nch; c++) {
        CP_WAIT0();
        __syncthreads();
        if (c + 1 < nch) { load_stage((c + 1) & 1, (c + 1) * 32); CP_COMMIT(); }

        uint32_t st = sbase + (c & 1) * 40960;
#pragma unroll
        for (int ks = 0; ks < 2; ks++) {
            uint32_t ah[4][4], al[4][4], bh[4][2], bl[4][2];
#pragma unroll
            for (int mt = 0; mt < 4; mt++) {
                uint32_t addr = st + (uint32_t)(wm * 64 + mt * 16 + (lane & 15)) * 80
                              + ((lane >> 4) * 16) + ks * 32;
                LDSM4(ah[mt], addr);
                LDSM4(al[mt], addr + 10240);
            }
#pragma unroll
            for (int nt = 0; nt < 4; nt++) {
                uint32_t addr = st + 20480 + (uint32_t)(wn * 32 + nt * 8 + (lane & 7)) * 80
                              + (((lane >> 3) & 1) * 16) + ks * 32;
                LDSM2(bh[nt], addr);
                LDSM2(bl[nt], addr + 10240);
            }
#pragma unroll
            for (int mt = 0; mt < 4; mt++)
#pragma unroll
                for (int nt = 0; nt < 4; nt++) {
                    MMA_BF16(acc[mt][nt], ah[mt], bh[nt]);
                    MMA_BF16(acc[mt][nt], al[mt], bh[nt]);
                    MMA_BF16(acc[mt][nt], ah[mt], bl[nt]);
                }
        }
    }

#pragma unroll
    for (int mt = 0; mt < 4; mt++) {
        int r0 = bm + wm * 64 + mt * 16 + (lane >> 2);
#pragma unroll
        for (int nt = 0; nt < 4; nt++) {
            int col = bn + wn * 32 + nt * 8 + (lane & 3) * 2;
            if (BF16OUT) {
#pragma unroll
                for (int hh = 0; hh < 2; hh++) {
                    int r = r0 + hh * 8;
                    if (r < M) {
                        float vx = acc[mt][nt][hh * 2], vy = acc[mt][nt][hh * 2 + 1];
                        __nv_bfloat16 hx = __float2bfloat16(vx);
                        __nv_bfloat16 hy = __float2bfloat16(vy);
                        __nv_bfloat16 lx = __float2bfloat16(vx - __bfloat162float(hx));
                        __nv_bfloat16 ly = __float2bfloat16(vy - __bfloat162float(hy));
                        size_t o = (size_t)r * Np + col;
                        *reinterpret_cast<__nv_bfloat162*>(Dhi + o) = __nv_bfloat162(hx, hy);
                        *reinterpret_cast<__nv_bfloat162*>(Dlo + o) = __nv_bfloat162(lx, ly);
                    }
                }
            } else {
                if (r0 < M) {
                    float2 v; v.x = acc[mt][nt][0]; v.y = acc[mt][nt][1];
                    *reinterpret_cast<float2*>(C + (size_t)r0 * Np + col) = v;
                }
                if (r0 + 8 < M) {
                    float2 v; v.x = acc[mt][nt][2]; v.y = acc[mt][nt][3];
                    *reinterpret_cast<float2*>(C + (size_t)(r0 + 8) * Np + col) = v;
                }
            }
        }
    }
}

// per-round GEMM with z offset: z<12 -> G1 tile, z>=12 -> V tile
__global__ void __launch_bounds__(256) mma_gemm_dual_kernel(
    const __nv_bfloat16* __restrict__ hvhi, const __nv_bfloat16* __restrict__ hvlo,
    const __nv_bfloat16* __restrict__ thi,  const __nv_bfloat16* __restrict__ tlo,
    const __nv_bfloat16* __restrict__ b1hi, const __nv_bfloat16* __restrict__ b1lo,
    const __nv_bfloat16* __restrict__ b2hi, const __nv_bfloat16* __restrict__ b2lo,
    float* __restrict__ G1, float* __restrict__ V, int z0)
{
    extern __shared__ __align__(128) char smem[];
    int z = z0 + blockIdx.x;
    int bm = blockIdx.y * 128;
    if (z < 12)
        gemm_core<false>(hvhi, hvlo, b1hi, b1lo, G1, nullptr, nullptr,
                         N_NODES, 1536, H, bm, z * 128, smem);
    else
        gemm_core<false>(thi, tlo, b2hi, b2lo, V, nullptr, nullptr,
                         N_NODES, TH, H, bm, (z - 12) * 128, smem);
}

// batched small GEMM with bf16 hi/lo epilogue
__global__ void __launch_bounds__(256) mma_gemm_batch_kernel() {
    extern __shared__ __align__(128) char smem[];
    int z = blockIdx.z;
    int t = z >> 1, half = z & 1;
    __nv_bfloat16* Dhi = half ? (g_B2_hi + (size_t)t * TH * H)
                              : (g_B1_hi + (size_t)t * 1536 * H);
    __nv_bfloat16* Dlo = half ? (g_B2_lo + (size_t)t * TH * H)
                              : (g_B1_lo + (size_t)t * 1536 * H);
    gemm_core<true>(g_Wih_hi + (size_t)t * TH * GH, g_Wih_lo + (size_t)t * TH * GH,
                    g_ms_hi + (size_t)t * GH * GH + (size_t)half * H * GH,
                    g_ms_lo + (size_t)t * GH * GH + (size_t)half * H * GH,
                    nullptr, Dhi, Dlo, TH, H, GH,
                    blockIdx.y * 128, blockIdx.x * 128, smem);
}

// ------------------------- cb/cw precompute -------------------------
__global__ void cbcw_kernel(const float* __restrict__ msg_w, const float* __restrict__ msg_b,
                            const float* __restrict__ w_ih) {
    int g = blockIdx.x * 8 + (threadIdx.x >> 5);
    if (g >= 2 * TH) return;
    int t = g / TH, j = g % TH, lane = threadIdx.x & 31;
    const float* wr = w_ih + ((size_t)t * TH + j) * GH;
    const float* mb = msg_b + t * GH;
    const float* wh = msg_w + (size_t)t * (2 * H + 1) * GH + (size_t)(2 * H) * GH;
    float s1 = 0.f, s2 = 0.f;
    for (int c = lane; c < GH; c += 32) {
        float w = wr[c];
        s1 += mb[c] * w;
        s2 += wh[c] * w;
    }
    s1 = warp_sum(s1); s2 = warp_sum(s2);
    if (lane == 0) { g_cb[g] = s1; g_cw[g] = s2; }
}

// ------------------------- init / CSR build -------------------------
__global__ void init_kernel() {
    int i = blockIdx.x * blockDim.x + threadIdx.x;
    if (i < N_NODES) { g_deg[i] = 0; g_sumhe[i] = 0.f; g_cursor[i] = 0; }
    if (i < NT * H) g_accv[i] = 0.f;
    if (i < NT) g_gsum[i] = 0.f;
}

__global__ void deg_kernel(const int* __restrict__ dst, const float* __restrict__ he) {
    int e = blockIdx.x * blockDim.x + threadIdx.x;
    if (e < N_EDGES) {
        atomicAdd(&g_deg[dst[e]], 1);
        atomicAdd(&g_sumhe[dst[e]], he[e]);
    }
}

__global__ void scan_kernel() {
    __shared__ int s[1024];
    __shared__ int carry;
    if (threadIdx.x == 0) { carry = 0; g_rowptr[0] = 0; }
    __syncthreads();
    for (int base = 0; base < N_NODES; base += 8192) {
        int idx0 = base + threadIdx.x * 8;
        int v[8]; int sum = 0;
#pragma unroll
        for (int i = 0; i < 8; i++) {
            int ii = idx0 + i;
            v[i] = (ii < N_NODES) ? g_deg[ii] : 0;
            sum += v[i];
        }
        s[threadIdx.x] = sum;
        __syncthreads();
        for (int d = 1; d < 1024; d <<= 1) {
            int t = (threadIdx.x >= d) ? s[threadIdx.x - d] : 0;
            __syncthreads();
            s[threadIdx.x] += t;
            __syncthreads();
        }
        int run = s[threadIdx.x] - sum + carry;
#pragma unroll
        for (int i = 0; i < 8; i++) {
            int ii = idx0 + i;
            run += v[i];
            if (ii < N_NODES) g_rowptr[ii + 1] = run;
        }
        __syncthreads();
        if (threadIdx.x == 1023) carry += s[1023];
        __syncthreads();
    }
}

__global__ void scatter_kernel(const int* __restrict__ src, const int* __restrict__ dst) {
    int e = blockIdx.x * blockDim.x + threadIdx.x;
    if (e < N_EDGES) {
        int d = dst[e];
        int slot = atomicAdd(&g_cursor[d], 1);
        g_csrsrc[g_rowptr[d] + slot] = src[e];
    }
}

// ------------------------- T aggregation + fused bf16 split -------------------------
__global__ void taggr_kernel(const float* __restrict__ hv) {
    int v = blockIdx.x;
    int c = threadIdx.x * 4;   // 64 threads
    int beg = g_rowptr[v], end = g_rowptr[v + 1];
    float ax = 0.f, ay = 0.f, az = 0.f, aw = 0.f;
    int p = beg;
    for (; p + 1 < end; p += 2) {
        int s0 = g_csrsrc[p], s1 = g_csrsrc[p + 1];
        float4 v0 = *reinterpret_cast<const float4*>(hv + (size_t)s0 * H + c);
        float4 v1 = *reinterpret_cast<const float4*>(hv + (size_t)s1 * H + c);
        ax += v0.x + v1.x; ay += v0.y + v1.y; az += v0.z + v1.z; aw += v0.w + v1.w;
    }
    if (p < end) {
        int s0 = g_csrsrc[p];
        float4 v0 = *reinterpret_cast<const float4*>(hv + (size_t)s0 * H + c);
        ax += v0.x; ay += v0.y; az += v0.z; aw += v0.w;
    }
    __nv_bfloat16 hx = __float2bfloat16(ax), hy = __float2bfloat16(ay);
    __nv_bfloat16 hz = __float2bfloat16(az), hw = __float2bfloat16(aw);
    __nv_bfloat16 lx = __float2bfloat16(ax - __bfloat162float(hx));
    __nv_bfloat16 ly = __float2bfloat16(ay - __bfloat162float(hy));
    __nv_bfloat16 lz = __float2bfloat16(az - __bfloat162float(hz));
    __nv_bfloat16 lw = __float2bfloat16(aw - __bfloat162float(hw));
    size_t off = (size_t)v * H + c;
    *reinterpret_cast<__nv_bfloat162*>(&g_Tb_hi[off])     = __nv_bfloat162(hx, hy);
    *reinterpret_cast<__nv_bfloat162*>(&g_Tb_hi[off + 2]) = __nv_bfloat162(hz, hw);
    *reinterpret_cast<__nv_bfloat162*>(&g_Tb_lo[off])     = __nv_bfloat162(lx, ly);
    *reinterpret_cast<__nv_bfloat162*>(&g_Tb_lo[off + 2]) = __nv_bfloat162(lz, lw);
}

// ------------------------- fused GRU (+ optional dest-score dot) -------------------------
template <bool WRITE_SPLIT, bool SCORE>
__global__ void gru2_kernel(const float* __restrict__ hv_in, float* __restrict__ hv_out,
                            const float* __restrict__ cb, const float* __restrict__ cw,
                            const float* __restrict__ b_ih, const float* __restrict__ b_hh,
                            const float* __restrict__ dw) {
    __shared__ float spart[8];
    int idx = blockIdx.x * blockDim.x + threadIdx.x;
    if (idx >= N_NODES * (H / 4)) return;
    int n = idx / (H / 4);
    int c = (idx % (H / 4)) * 4;
    float deg = (float)(g_rowptr[n + 1] - g_rowptr[n]);
    float sh = g_sumhe[n];
    const float* G1 = g_G1 + (size_t)n * 1536;
    const float* V = g_V + (size_t)n * TH;
#define LD4(p) (*reinterpret_cast<const float4*>(p))
    float4 Ur = LD4(G1 + c),        Uz = LD4(G1 + 256 + c),  Un = LD4(G1 + 512 + c);
    float4 Hr = LD4(G1 + 768 + c),  Hz = LD4(G1 + 1024 + c), Hn = LD4(G1 + 1280 + c);
    float4 Vr = LD4(V + c),         Vz = LD4(V + 256 + c),   Vn = LD4(V + 512 + c);
    float4 cbr = LD4(cb + c), cbz = LD4(cb + 256 + c), cbn = LD4(cb + 512 + c);
    float4 cwr = LD4(cw + c), cwz = LD4(cw + 256 + c), cwn = LD4(cw + 512 + c);
    float4 bir = LD4(b_ih + c), biz = LD4(b_ih + 256 + c), bin_ = LD4(b_ih + 512 + c);
    float4 bhr = LD4(b_hh + c), bhz = LD4(b_hh + 256 + c), bhn = LD4(b_hh + 512 + c);
    float4 hc = LD4(hv_in + (size_t)n * H + c);
#undef LD4
    float4 o;
#define GRU1(X) { \
    float gir = deg * (Ur.X + cbr.X) + Vr.X + sh * cwr.X + bir.X; \
    float giz = deg * (Uz.X + cbz.X) + Vz.X + sh * cwz.X + biz.X; \
    float gin = deg * (Un.X + cbn.X) + Vn.X + sh * cwn.X + bin_.X; \
    float rr = 1.f / (1.f + expf(-(gir + Hr.X + bhr.X))); \
    float zz = 1.f / (1.f + expf(-(giz + Hz.X + bhz.X))); \
    float nn = tanhf(gin + rr * (Hn.X + bhn.X)); \
    o.X = (1.f - zz) * nn + zz * hc.X; }
    GRU1(x) GRU1(y) GRU1(z) GRU1(w)
#undef GRU1
    *reinterpret_cast<float4*>(hv_out + (size_t)n * H + c) = o;
    if (WRITE_SPLIT) {
        __nv_bfloat16 hx = __float2bfloat16(o.x), hy = __float2bfloat16(o.y);
        __nv_bfloat16 hz_ = __float2bfloat16(o.z), hw = __float2bfloat16(o.w);
        __nv_bfloat16 lx = __float2bfloat16(o.x - __bfloat162float(hx));
        __nv_bfloat16 ly = __float2bfloat16(o.y - __bfloat162float(hy));
        __nv_bfloat16 lz = __float2bfloat16(o.z - __bfloat162float(hz_));
        __nv_bfloat16 lw = __float2bfloat16(o.w - __bfloat162float(hw));
        size_t boff = (size_t)n * H + c;
        *reinterpret_cast<__nv_bfloat162*>(&g_hvb_hi[boff])     = __nv_bfloat162(hx, hy);
        *reinterpret_cast<__nv_bfloat162*>(&g_hvb_hi[boff + 2]) = __nv_bfloat162(hz_, hw);
        *reinterpret_cast<__nv_bfloat162*>(&g_hvb_lo[boff])     = __nv_bfloat162(lx, ly);
        *reinterpret_cast<__nv_bfloat162*>(&g_hvb_lo[boff + 2]) = __nv_bfloat162(lz, lw);
    }
    if (SCORE) {
        float s = o.x * dw[c] + o.y * dw[c + 1] + o.z * dw[c + 2] + o.w * dw[c + 3];
        s = warp_sum(s);
        int wid = threadIdx.x >> 5;
        if ((threadIdx.x & 31) == 0) spart[wid] = s;
        __syncthreads();
        if ((threadIdx.x & 63) == 0 && n < N_NODES - 1)
            g_scores[n] = spart[wid] + spart[wid + 1];
    }
}

// ------------------------- graph embed -------------------------
__global__ void gate_kernel(const float* __restrict__ hv, const int* __restrict__ ntype,
                            const float* __restrict__ gate_w, const float* __restrict__ gate_b) {
    __shared__ float sacc[NT * H];
    __shared__ float ssum[NT];
    int tid = threadIdx.x;
    for (int i = tid; i < NT * H; i += 256) sacc[i] = 0.f;
    if (tid < NT) ssum[tid] = 0.f;
    __syncthreads();
    int warp = tid >> 5, lane = tid & 31;
    int n = blockIdx.x * 8 + warp;
    if (n < N_NODES) {
        int t = ntype[n];
        const float* hrow = hv + (size_t)n * H;
        const float* gw = gate_w + t * H;
        float dot = 0.f;
        for (int k = lane; k < H; k += 32) dot += hrow[k] * gw[k];
        dot = warp_sum(dot);
        dot = __shfl_sync(0xffffffffu, dot, 0);
        float g = 1.f / (1.f + expf(-(dot + gate_b[t])));
        for (int k = lane; k < H; k += 32) atomicAdd(&sacc[t * H + k], g * hrow[k]);
        if (lane == 0) atomicAdd(&ssum[t], g);
    }
    __syncthreads();
    for (int i = tid; i < NT * H; i += 256) if (sacc[i] != 0.f) atomicAdd(&g_accv[i], sacc[i]);
    if (tid < NT) atomicAdd(&g_gsum[tid], ssum[tid]);
}

// phase A: per-(col-slab, type) partial GEMV
__global__ void gembed_part_kernel(const float* __restrict__ tog_w) {
    int c = blockIdx.x * 128 + threadIdx.x;
    int t = blockIdx.y;
    const float* W = tog_w + (size_t)t * H * GH;
    const float* av = g_accv + t * H;
    float acc = 0.f;
#pragma unroll 4
    for (int k = 0; k < H; k++) acc += av[k] * W[(size_t)k * GH + c];
    g_gpart[t * GH + c] = acc;
}

// phase B: combine partials + bias terms
__global__ void gembed_final_kernel(const float* __restrict__ tog_b, float* __restrict__ outg) {
    int c = threadIdx.x;  // 512
    float acc = 0.f;
#pragma unroll
    for (int t = 0; t < NT; t++)
        acc += g_gpart[t * GH + c] + g_gsum[t] * tog_b[t * GH + c];
    outg[c] = acc;
}

// ------------------------- merged tail heads -------------------------
__global__ void heads_kernel(const float* __restrict__ ge, const float* __restrict__ hv,
                             const float* __restrict__ addn_w, const float* __restrict__ addn_b,
                             const float* __restrict__ nte, const float* __restrict__ init_w,
                             const float* __restrict__ init_b,
                             const float* __restrict__ adde_w, const float* __restrict__ adde_b,
                             float* __restrict__ out) {
    int tid = threadIdx.x;
    if (blockIdx.x == 0) {
        __shared__ float logits[4];
        if (tid < 128) {
            int t = tid >> 5, lane = tid & 31;
            float dot = 0.f;
            for (int k = lane; k < GH; k += 32) dot += ge[k] * addn_w[k * 4 + t];
            dot = warp_sum(dot);
            if (lane == 0) logits[t] = dot + addn_b[t];
        }
        __syncthreads();
        if (tid == 0) {
            float m = fmaxf(fmaxf(logits[0], logits[1]), fmaxf(logits[2], logits[3]));
            float s = 0.f;
            for (int i = 0; i < 4; i++) s += expf(logits[i] - m);
            float l = logf(s);
            for (int i = 0; i < 4; i++) out[OFF_NLOGP + i] = logits[i] - m - l;
        }
    } else if (blockIdx.x == 1) {
        int c = tid;
        float a0 = init_b[c], a1 = 0.f, a2 = 0.f, a3 = 0.f;
#pragma unroll 4
        for (int k = 0; k < H; k += 4) {
            a0 += nte[k] * init_w[(size_t)k * H + c];
            a1 += nte[k + 1] * init_w[(size_t)(k + 1) * H + c];
            a2 += nte[k + 2] * init_w[(size_t)(k + 2) * H + c];
            a3 += nte[k + 3] * init_w[(size_t)(k + 3) * H + c];
        }
#pragma unroll 4
        for (int k = 0; k < GH; k += 4) {
            a0 += ge[k] * init_w[(size_t)(H + k) * H + c];
            a1 += ge[k + 1] * init_w[(size_t)(H + k + 1) * H + c];
            a2 += ge[k + 2] * init_w[(size_t)(H + k + 2) * H + c];
            a3 += ge[k + 3] * init_w[(size_t)(H + k + 3) * H + c];
        }
        out[OFF_HVINIT + c] = a0 + a1 + a2 + a3;
    } else {
        if (tid < 32) {
            const float* se = hv + (size_t)(N_NODES - 1) * H;
            float dot = 0.f;
            for (int k = tid; k < GH; k += 32) dot += ge[k] * adde_w[k];
            for (int k = tid; k < H; k += 32) dot += se[k] * adde_w[GH + k];
            dot = warp_sum(dot);
            if (tid == 0) out[OFF_EDGE] = dot + adde_b[0];
        }
    }
}

// ------------------------- dest logsoftmax (cst cancels) -------------------------
__global__ void destreduce_kernel() {
    __shared__ float s[1024];
    int tid = threadIdx.x;
    float m = -INFINITY;
    for (int i = tid; i < N_NODES - 1; i += 1024) m = fmaxf(m, g_scores[i]);
    s[tid] = m; __syncthreads();
    for (int d = 512; d; d >>= 1) {
        if (tid < d) s[tid] = fmaxf(s[tid], s[tid + d]);
        __syncthreads();
    }
    float M = s[0];
    __syncthreads();
    float sum = 0.f;
    for (int i = tid; i < N_NODES - 1; i += 1024) sum += expf(g_scores[i] - M);
    s[tid] = sum; __syncthreads();
    for (int d = 512; d; d >>= 1) {
        if (tid < d) s[tid] += s[tid + d];
        __syncthreads();
    }
    if (tid == 0) { g_red[0] = M; g_red[1] = logf(s[0]); }
}

__global__ void destwrite_kernel(float* __restrict__ out) {
    int i = blockIdx.x * blockDim.x + threadIdx.x;
    if (i < N_NODES - 1) out[i] = g_scores[i] - g_red[0] - g_red[1];
}

// ------------------------- host -------------------------
extern "C" void kernel_launch(void* const* d_in, const int* in_sizes, int n_in,
                              void* d_out, int out_size) {
    const float* hv0   = (const float*)d_in[0];
    const float* he    = (const float*)d_in[1];
    const int*   ntype = (const int*)d_in[2];
    const int*   src   = (const int*)d_in[3];
    const int*   dst   = (const int*)d_in[4];
    const float* msg_w = (const float*)d_in[5];
    const float* msg_b = (const float*)d_in[6];
    const float* w_ih  = (const float*)d_in[7];
    const float* b_ih  = (const float*)d_in[8];
    const float* w_hh  = (const float*)d_in[9];
    const float* b_hh  = (const float*)d_in[10];
    const float* gate_w = (const float*)d_in[11];
    const float* gate_b = (const float*)d_in[12];
    const float* tog_w  = (const float*)d_in[13];
    const float* tog_b  = (const float*)d_in[14];
    const float* addn_w = (const float*)d_in[15];
    const float* addn_b = (const float*)d_in[16];
    const float* nte    = (const float*)d_in[17];
    const float* init_w = (const float*)d_in[18];
    const float* init_b = (const float*)d_in[19];
    const float* adde_w = (const float*)d_in[20];
    const float* adde_b = (const float*)d_in[21];
    const float* dest_w = (const float*)d_in[22];
    const float* dest_b = (const float*)d_in[23];
    float* out = (float*)d_out;

    void *p;
    cudaGetSymbolAddress(&p, g_G1);      float* G1 = (float*)p;
    cudaGetSymbolAddress(&p, g_V);       float* V = (float*)p;
    cudaGetSymbolAddress(&p, g_hv1);     float* Hv1 = (float*)p;
    cudaGetSymbolAddress(&p, g_cb);      float* Cb = (float*)p;
    cudaGetSymbolAddress(&p, g_cw);      float* Cw = (float*)p;
    cudaGetSymbolAddress(&p, g_hvb_hi);  __nv_bfloat16* HvHi = (__nv_bfloat16*)p;
    cudaGetSymbolAddress(&p, g_hvb_lo);  __nv_bfloat16* HvLo = (__nv_bfloat16*)p;
    cudaGetSymbolAddress(&p, g_Tb_hi);   __nv_bfloat16* TbHi = (__nv_bfloat16*)p;
    cudaGetSymbolAddress(&p, g_Tb_lo);   __nv_bfloat16* TbLo = (__nv_bfloat16*)p;
    cudaGetSymbolAddress(&p, g_B1_hi);   __nv_bfloat16* B1Hi = (__nv_bfloat16*)p;
    cudaGetSymbolAddress(&p, g_B1_lo);   __nv_bfloat16* B1Lo = (__nv_bfloat16*)p;
    cudaGetSymbolAddress(&p, g_B2_hi);   __nv_bfloat16* B2Hi = (__nv_bfloat16*)p;
    cudaGetSymbolAddress(&p, g_B2_lo);   __nv_bfloat16* B2Lo = (__nv_bfloat16*)p;

    // Streams/events created ONCE on the first (uncaptured) call, reused after.
    static cudaStream_t sA = nullptr, sB = nullptr;
    static cudaEvent_t evFork, evPrep, evCbcw, evT0, evV0, evG, evV1, evTail, evD;
    static bool s_init = false;
    if (!s_init) {
        cudaStreamCreateWithFlags(&sA, cudaStreamNonBlocking);
        cudaStreamCreateWithFlags(&sB, cudaStreamNonBlocking);
        cudaEventCreateWithFlags(&evFork, cudaEventDisableTiming);
        cudaEventCreateWithFlags(&evPrep, cudaEventDisableTiming);
        cudaEventCreateWithFlags(&evCbcw, cudaEventDisableTiming);
        cudaEventCreateWithFlags(&evT0,   cudaEventDisableTiming);
        cudaEventCreateWithFlags(&evV0,   cudaEventDisableTiming);
        cudaEventCreateWithFlags(&evG,    cudaEventDisableTiming);
        cudaEventCreateWithFlags(&evV1,   cudaEventDisableTiming);
        cudaEventCreateWithFlags(&evTail, cudaEventDisableTiming);
        cudaEventCreateWithFlags(&evD,    cudaEventDisableTiming);
        cudaFuncSetAttribute(mma_gemm_dual_kernel,
                             cudaFuncAttributeMaxDynamicSharedMemorySize, GEMM_SMEM);
        cudaFuncSetAttribute(mma_gemm_batch_kernel,
                             cudaFuncAttributeMaxDynamicSharedMemorySize, GEMM_SMEM);
        s_init = true;
    }

    const int MT = (N_NODES + 127) / 128;  // 157

    // ---- fork prep branch onto sB: hv0 split + weight splits + batch GEMM ----
    cudaEventRecord(evFork, 0);
    cudaStreamWaitEvent(sB, evFork, 0);
    split_kernel<<<(N_NODES * H + 255) / 256, 256, 0, sB>>>(hv0, HvHi, HvLo, N_NODES * H);
    {
        const int total = 2 * (GH * GH) + 2 * (TH * GH) + 2 * (TH * H);
        prep_split_kernel<<<(total + 255) / 256, 256, 0, sB>>>(msg_w, w_ih, w_hh);
    }
    mma_gemm_batch_kernel<<<dim3(H / 128, TH / 128, 4), 256, GEMM_SMEM, sB>>>();
    cudaEventRecord(evPrep, sB);                 // gates round GEMMs (B1/B2 ready)
    cbcw_kernel<<<(2 * TH + 7) / 8, 256, 0, sB>>>(msg_w, msg_b, w_ih);
    cudaEventRecord(evCbcw, sB);                 // gates gru2 only (cb/cw ready)

    // ---- main: CSR build ----
    init_kernel<<<(N_NODES + 255) / 256, 256>>>();
    deg_kernel<<<(N_EDGES + 255) / 256, 256>>>(dst, he);
    scan_kernel<<<1, 1024>>>();
    scatter_kernel<<<(N_EDGES + 255) / 256, 256>>>(src, dst);
    cudaEventRecord(evT0, 0);

    // ---- round 0 ----
    {
        const __nv_bfloat16 *b1h = B1Hi, *b1l = B1Lo, *b2h = B2Hi, *b2l = B2Lo;
        cudaStreamWaitEvent(sA, evT0, 0);
        taggr_kernel<<<N_NODES, 64, 0, sA>>>(hv0);
        cudaStreamWaitEvent(sA, evPrep, 0);
        mma_gemm_dual_kernel<<<dim3(6, MT), 256, GEMM_SMEM, sA>>>(
            HvHi, HvLo, TbHi, TbLo, b1h, b1l, b2h, b2l, G1, V, 12);
        cudaEventRecord(evV0, sA);
        cudaStreamWaitEvent(0, evPrep, 0);
        mma_gemm_dual_kernel<<<dim3(12, MT), 256, GEMM_SMEM>>>(
            HvHi, HvLo, TbHi, TbLo, b1h, b1l, b2h, b2l, G1, V, 0);
        cudaStreamWaitEvent(0, evV0, 0);
        cudaStreamWaitEvent(0, evCbcw, 0);
        gru2_kernel<true, false><<<(N_NODES * (H / 4) + 255) / 256, 256>>>(
            hv0, Hv1, Cb, Cw, b_ih, b_hh, dest_w);
        cudaEventRecord(evG, 0);
    }

    // ---- round 1 ----
    {
        const __nv_bfloat16 *b1h = B1Hi + (size_t)1536 * H, *b1l = B1Lo + (size_t)1536 * H;
        const __nv_bfloat16 *b2h = B2Hi + (size_t)TH * H,   *b2l = B2Lo + (size_t)TH * H;
        cudaStreamWaitEvent(sA, evG, 0);
        taggr_kernel<<<N_NODES, 64, 0, sA>>>(Hv1);
        mma_gemm_dual_kernel<<<dim3(6, MT), 256, GEMM_SMEM, sA>>>(
            HvHi, HvLo, TbHi, TbLo, b1h, b1l, b2h, b2l, G1, V, 12);
        cudaEventRecord(evV1, sA);
        mma_gemm_dual_kernel<<<dim3(12, MT), 256, GEMM_SMEM>>>(
            HvHi, HvLo, TbHi, TbLo, b1h, b1l, b2h, b2l, G1, V, 0);
        cudaStreamWaitEvent(0, evV1, 0);
        gru2_kernel<false, true><<<(N_NODES * (H / 4) + 255) / 256, 256>>>(
            Hv1, out, Cb + TH, Cw + TH, b_ih + TH, b_hh + TH, dest_w);
        cudaEventRecord(evTail, 0);
    }

    // ---- tail: dest logsoftmax on sA, embed chain on main ----
    cudaStreamWaitEvent(sA, evTail, 0);
    destreduce_kernel<<<1, 1024, 0, sA>>>();
    destwrite_kernel<<<(N_NODES - 1 + 255) / 256, 256, 0, sA>>>(out + OFF_DEST);
    cudaEventRecord(evD, sA);

    gate_kernel<<<(N_NODES + 7) / 8, 256>>>(out, ntype, gate_w, gate_b);
    gembed_part_kernel<<<dim3(GH / 128, NT), 128>>>(tog_w);
    gembed_final_kernel<<<1, 512>>>(tog_b, out + OFF_GEMB);
    heads_kernel<<<3, 256>>>(out + OFF_GEMB, out, addn_w, addn_b,
                             nte, init_w, init_b, adde_w, adde_b, out);

    // join everything back to the main stream before capture ends
    cudaStreamWaitEvent(0, evD, 0);
}

// round 15
// speedup vs baseline: 1.1259x; 1.0200x over previous
#include <cuda_runtime.h>
#include <cuda_bf16.h>
#include <math.h>
#include <stdint.h>

#define N_NODES 20000
#define N_EDGES 320000
#define H 256
#define GH 512
#define TH 768
#define NT 3

#define OFF_GEMB   5120000
#define OFF_NLOGP  5120512
#define OFF_HVINIT 5120516
#define OFF_EDGE   5120772
#define OFF_DEST   5120773

// ------------------------- scratch -------------------------
__device__ __align__(16) float g_G1[N_NODES * 1536];
__device__ __align__(16) float g_V[N_NODES * TH];
__device__ __align__(16) float g_hv1[N_NODES * H];
__device__ __align__(16) float g_cb[2 * TH];
__device__ __align__(16) float g_cw[2 * TH];
__device__ int   g_deg[N_NODES];
__device__ float g_sumhe[N_NODES];
__device__ int   g_rowptr[N_NODES + 1];
__device__ int   g_cursor[N_NODES];
__device__ int   g_csrsrc[N_EDGES];
__device__ float g_accv[NT * H];
__device__ float g_gsum[NT];
__device__ float g_gpart[NT * GH];
__device__ float g_scores[N_NODES];
__device__ float g_red[4];

__device__ __align__(16) __nv_bfloat16 g_hvb_hi[N_NODES * H];
__device__ __align__(16) __nv_bfloat16 g_hvb_lo[N_NODES * H];
__device__ __align__(16) __nv_bfloat16 g_Tb_hi[N_NODES * H];
__device__ __align__(16) __nv_bfloat16 g_Tb_lo[N_NODES * H];
__device__ __align__(16) __nv_bfloat16 g_Wih_hi[2 * TH * GH];
__device__ __align__(16) __nv_bfloat16 g_Wih_lo[2 * TH * GH];
__device__ __align__(16) __nv_bfloat16 g_ms_hi[2 * GH * GH];
__device__ __align__(16) __nv_bfloat16 g_ms_lo[2 * GH * GH];
__device__ __align__(16) __nv_bfloat16 g_B1_hi[2 * 1536 * H];
__device__ __align__(16) __nv_bfloat16 g_B1_lo[2 * 1536 * H];
__device__ __align__(16) __nv_bfloat16 g_B2_hi[2 * TH * H];
__device__ __align__(16) __nv_bfloat16 g_B2_lo[2 * TH * H];

__device__ __forceinline__ float warp_sum(float v) {
#pragma unroll
    for (int o = 16; o; o >>= 1) v += __shfl_xor_sync(0xffffffffu, v, o);
    return v;
}

__device__ __forceinline__ uint32_t smem_u32(const void* p) {
    uint32_t a;
    asm("{ .reg .u64 t; cvta.to.shared.u64 t, %1; cvt.u32.u64 %0, t; }" : "=r"(a) : "l"(p));
    return a;
}

// ------------------------- tensor macros -------------------------
#define CP_ASYNC(dst, src, sz) \
    asm volatile("cp.async.ca.shared.global [%0], [%1], 16, %2;" \
                 :: "r"(dst), "l"(src), "r"(sz) : "memory")
#define CP_COMMIT()  asm volatile("cp.async.commit_group;" ::: "memory")
#define CP_WAIT0()   asm volatile("cp.async.wait_group 0;" ::: "memory")

#define LDSM4(r, a) \
    asm volatile("ldmatrix.sync.aligned.m8n8.x4.shared.b16 {%0,%1,%2,%3}, [%4];" \
                 : "=r"((r)[0]), "=r"((r)[1]), "=r"((r)[2]), "=r"((r)[3]) : "r"(a))
#define LDSM2(r, a) \
    asm volatile("ldmatrix.sync.aligned.m8n8.x2.shared.b16 {%0,%1}, [%2];" \
                 : "=r"((r)[0]), "=r"((r)[1]) : "r"(a))
#define MMA_BF16(c, a, b) \
    asm volatile("mma.sync.aligned.m16n8k16.row.col.f32.bf16.bf16.f32 " \
                 "{%0,%1,%2,%3}, {%4,%5,%6,%7}, {%8,%9}, {%0,%1,%2,%3};" \
                 : "+f"((c)[0]), "+f"((c)[1]), "+f"((c)[2]), "+f"((c)[3]) \
                 : "r"((a)[0]), "r"((a)[1]), "r"((a)[2]), "r"((a)[3]), \
                   "r"((b)[0]), "r"((b)[1]))

// ------------------------- bf16 split (hv0 only) -------------------------
__global__ void split_kernel(const float* __restrict__ in,
                             __nv_bfloat16* __restrict__ hi,
                             __nv_bfloat16* __restrict__ lo, int n) {
    int i = blockIdx.x * blockDim.x + threadIdx.x;
    if (i < n) {
        float x = in[i];
        __nv_bfloat16 h = __float2bfloat16(x);
        float r = x - __bfloat162float(h);
        hi[i] = h;
        lo[i] = __float2bfloat16(r);
    }
}

// merged weight-split prep (one launch)
__global__ void prep_split_kernel(const float* __restrict__ msg_w,
                                  const float* __restrict__ w_ih,
                                  const float* __restrict__ w_hh) {
    const int nMS = GH * GH, nWI = TH * GH, nWH = TH * H;
    int i = blockIdx.x * blockDim.x + threadIdx.x;
    float x;
    __nv_bfloat16 *dh, *dl;
    if (i < 2 * nMS) {
        int t = i / nMS, k = i % nMS;
        x = msg_w[(size_t)t * (2 * H + 1) * GH + k];
        dh = g_ms_hi + i; dl = g_ms_lo + i;
    } else if (i < 2 * nMS + 2 * nWI) {
        int j = i - 2 * nMS;
        x = w_ih[j];
        dh = g_Wih_hi + j; dl = g_Wih_lo + j;
    } else if (i < 2 * nMS + 2 * nWI + 2 * nWH) {
        int j = i - 2 * nMS - 2 * nWI;
        int t = j / nWH, k = j % nWH;
        x = w_hh[j];
        size_t off = (size_t)t * 1536 * H + (size_t)TH * H + k;
        dh = g_B1_hi + off; dl = g_B1_lo + off;
    } else return;
    __nv_bfloat16 h = __float2bfloat16(x);
    *dh = h;
    *dl = __float2bfloat16(x - __bfloat162float(h));
}

// ------------------------- mma.sync bf16x3 GEMM core -------------------------
#define GEMM_SMEM 81920

template <bool BF16OUT>
__device__ __forceinline__ void gemm_core(
    const __nv_bfloat16* __restrict__ Ahi, const __nv_bfloat16* __restrict__ Alo,
    const __nv_bfloat16* __restrict__ Bhi, const __nv_bfloat16* __restrict__ Blo,
    float* __restrict__ C, __nv_bfloat16* __restrict__ Dhi, __nv_bfloat16* __restrict__ Dlo,
    int M, int Np, int K, int bm, int bn, char* smem)
{
    const int tid = threadIdx.x;
    const int wid = tid >> 5, lane = tid & 31;
    const int wm = wid & 1, wn = wid >> 1;
    const uint32_t sbase = smem_u32(smem);

    float acc[4][4][4];
#pragma unroll
    for (int i = 0; i < 4; i++)
#pragma unroll
        for (int j = 0; j < 4; j++) {
            acc[i][j][0] = 0.f; acc[i][j][1] = 0.f;
            acc[i][j][2] = 0.f; acc[i][j][3] = 0.f;
        }

    const int nch = K / 32;

    auto load_stage = [&](int s, int k0) {
        uint32_t st = sbase + s * 40960;
#pragma unroll
        for (int it = 0; it < 2; it++) {
            int u = tid + it * 256;
            int row = u >> 2, g = u & 3;
            uint32_t d = st + row * 80 + g * 16;
            int gr = bm + row;
            size_t aoff = (size_t)(gr < M ? gr : 0) * K + k0 + g * 8;
            uint32_t asz = (gr < M) ? 16u : 0u;
            CP_ASYNC(d,         Ahi + aoff, asz);
            CP_ASYNC(d + 10240, Alo + aoff, asz);
            size_t boff = (size_t)(bn + row) * K + k0 + g * 8;
            CP_ASYNC(d + 20480, Bhi + boff, 16u);
            CP_ASYNC(d + 30720, Blo + boff, 16u);
        }
    };

    load_stage(0, 0);
    CP_COMMIT();

    for (int c = 0; c < nch; c++) {
        CP_WAIT0();
        __syncthreads();
        if (c + 1 < nch) { load_stage((c + 1) & 1, (c + 1) * 32); CP_COMMIT(); }

        uint32_t st = sbase + (c & 1) * 40960;
#pragma unroll
        for (int ks = 0; ks < 2; ks++) {
            uint32_t ah[4][4], al[4][4], bh[4][2], bl[4][2];
#pragma unroll
            for (int mt = 0; mt < 4; mt++) {
                uint32_t addr = st + (uint32_t)(wm * 64 + mt * 16 + (lane & 15)) * 80
                              + ((lane >> 4) * 16) + ks * 32;
                LDSM4(ah[mt], addr);
                LDSM4(al[mt], addr + 10240);
            }
#pragma unroll
            for (int nt = 0; nt < 4; nt++) {
                uint32_t addr = st + 20480 + (uint32_t)(wn * 32 + nt * 8 + (lane & 7)) * 80
                              + (((lane >> 3) & 1) * 16) + ks * 32;
                LDSM2(bh[nt], addr);
                LDSM2(bl[nt], addr + 10240);
            }
#pragma unroll
            for (int mt = 0; mt < 4; mt++)
#pragma unroll
                for (int nt = 0; nt < 4; nt++) {
                    MMA_BF16(acc[mt][nt], ah[mt], bh[nt]);
                    MMA_BF16(acc[mt][nt], al[mt], bh[nt]);
                    MMA_BF16(acc[mt][nt], ah[mt], bl[nt]);
                }
        }
    }

#pragma unroll
    for (int mt = 0; mt < 4; mt++) {
        int r0 = bm + wm * 64 + mt * 16 + (lane >> 2);
#pragma unroll
        for (int nt = 0; nt < 4; nt++) {
            int col = bn + wn * 32 + nt * 8 + (lane & 3) * 2;
            if (BF16OUT) {
#pragma unroll
                for (int hh = 0; hh < 2; hh++) {
                    int r = r0 + hh * 8;
                    if (r < M) {
                        float vx = acc[mt][nt][hh * 2], vy = acc[mt][nt][hh * 2 + 1];
                        __nv_bfloat16 hx = __float2bfloat16(vx);
                        __nv_bfloat16 hy = __float2bfloat16(vy);
                        __nv_bfloat16 lx = __float2bfloat16(vx - __bfloat162float(hx));
                        __nv_bfloat16 ly = __float2bfloat16(vy - __bfloat162float(hy));
                        size_t o = (size_t)r * Np + col;
                        *reinterpret_cast<__nv_bfloat162*>(Dhi + o) = __nv_bfloat162(hx, hy);
                        *reinterpret_cast<__nv_bfloat162*>(Dlo + o) = __nv_bfloat162(lx, ly);
                    }
                }
            } else {
                if (r0 < M) {
                    float2 v; v.x = acc[mt][nt][0]; v.y = acc[mt][nt][1];
                    *reinterpret_cast<float2*>(C + (size_t)r0 * Np + col) = v;
                }
                if (r0 + 8 < M) {
                    float2 v; v.x = acc[mt][nt][2]; v.y = acc[mt][nt][3];
                    *reinterpret_cast<float2*>(C + (size_t)(r0 + 8) * Np + col) = v;
                }
            }
        }
    }
}

// per-round GEMM with z offset: z<12 -> G1 tile, z>=12 -> V tile
__global__ void __launch_bounds__(256) mma_gemm_dual_kernel(
    const __nv_bfloat16* __restrict__ hvhi, const __nv_bfloat16* __restrict__ hvlo,
    const __nv_bfloat16* __restrict__ thi,  const __nv_bfloat16* __restrict__ tlo,
    const __nv_bfloat16* __restrict__ b1hi, const __nv_bfloat16* __restrict__ b1lo,
    const __nv_bfloat16* __restrict__ b2hi, const __nv_bfloat16* __restrict__ b2lo,
    float* __restrict__ G1, float* __restrict__ V, int z0)
{
    extern __shared__ __align__(128) char smem[];
    int z = z0 + blockIdx.x;
    int bm = blockIdx.y * 128;
    if (z < 12)
        gemm_core<false>(hvhi, hvlo, b1hi, b1lo, G1, nullptr, nullptr,
                         N_NODES, 1536, H, bm, z * 128, smem);
    else
        gemm_core<false>(thi, tlo, b2hi, b2lo, V, nullptr, nullptr,
                         N_NODES, TH, H, bm, (z - 12) * 128, smem);
}

// batched small GEMM with bf16 hi/lo epilogue
__global__ void __launch_bounds__(256) mma_gemm_batch_kernel() {
    extern __shared__ __align__(128) char smem[];
    int z = blockIdx.z;
    int t = z >> 1, half = z & 1;
    __nv_bfloat16* Dhi = half ? (g_B2_hi + (size_t)t * TH * H)
                              : (g_B1_hi + (size_t)t * 1536 * H);
    __nv_bfloat16* Dlo = half ? (g_B2_lo + (size_t)t * TH * H)
                              : (g_B1_lo + (size_t)t * 1536 * H);
    gemm_core<true>(g_Wih_hi + (size_t)t * TH * GH, g_Wih_lo + (size_t)t * TH * GH,
                    g_ms_hi + (size_t)t * GH * GH + (size_t)half * H * GH,
                    g_ms_lo + (size_t)t * GH * GH + (size_t)half * H * GH,
                    nullptr, Dhi, Dlo, TH, H, GH,
                    blockIdx.y * 128, blockIdx.x * 128, smem);
}

// ------------------------- cb/cw precompute -------------------------
__global__ void cbcw_kernel(const float* __restrict__ msg_w, const float* __restrict__ msg_b,
                            const float* __restrict__ w_ih) {
    int g = blockIdx.x * 8 + (threadIdx.x >> 5);
    if (g >= 2 * TH) return;
    int t = g / TH, j = g % TH, lane = threadIdx.x & 31;
    const float* wr = w_ih + ((size_t)t * TH + j) * GH;
    const float* mb = msg_b + t * GH;
    const float* wh = msg_w + (size_t)t * (2 * H + 1) * GH + (size_t)(2 * H) * GH;
    float s1 = 0.f, s2 = 0.f;
    for (int c = lane; c < GH; c += 32) {
        float w = wr[c];
        s1 += mb[c] * w;
        s2 += wh[c] * w;
    }
    s1 = warp_sum(s1); s2 = warp_sum(s2);
    if (lane == 0) { g_cb[g] = s1; g_cw[g] = s2; }
}

// ------------------------- init / CSR build -------------------------
__global__ void init_kernel() {
    int i = blockIdx.x * blockDim.x + threadIdx.x;
    if (i < N_NODES) { g_deg[i] = 0; g_sumhe[i] = 0.f; g_cursor[i] = 0; }
    if (i < NT * H) g_accv[i] = 0.f;
    if (i < NT) g_gsum[i] = 0.f;
}

__global__ void deg_kernel(const int* __restrict__ dst, const float* __restrict__ he) {
    int e = blockIdx.x * blockDim.x + threadIdx.x;
    if (e < N_EDGES) {
        atomicAdd(&g_deg[dst[e]], 1);
        atomicAdd(&g_sumhe[dst[e]], he[e]);
    }
}

__global__ void scan_kernel() {
    __shared__ int s[1024];
    __shared__ int carry;
    if (threadIdx.x == 0) { carry = 0; g_rowptr[0] = 0; }
    __syncthreads();
    for (int base = 0; base < N_NODES; base += 8192) {
        int idx0 = base + threadIdx.x * 8;
        int v[8]; int sum = 0;
#pragma unroll
        for (int i = 0; i < 8; i++) {
            int ii = idx0 + i;
            v[i] = (ii < N_NODES) ? g_deg[ii] : 0;
            sum += v[i];
        }
        s[threadIdx.x] = sum;
        __syncthreads();
        for (int d = 1; d < 1024; d <<= 1) {
            int t = (threadIdx.x >= d) ? s[threadIdx.x - d] : 0;
            __syncthreads();
            s[threadIdx.x] += t;
            __syncthreads();
        }
        int run = s[threadIdx.x] - sum + carry;
#pragma unroll
        for (int i = 0; i < 8; i++) {
            int ii = idx0 + i;
            run += v[i];
            if (ii < N_NODES) g_rowptr[ii + 1] = run;
        }
        __syncthreads();
        if (threadIdx.x == 1023) carry += s[1023];
        __syncthreads();
    }
}

__global__ void scatter_kernel(const int* __restrict__ src, const int* __restrict__ dst) {
    int e = blockIdx.x * blockDim.x + threadIdx.x;
    if (e < N_EDGES) {
        int d = dst[e];
        int slot = atomicAdd(&g_cursor[d], 1);
        g_csrsrc[g_rowptr[d] + slot] = src[e];
    }
}

// ------------------------- T aggregation + fused bf16 split -------------------------
__global__ void taggr_kernel(const float* __restrict__ hv) {
    int v = blockIdx.x;
    int c = threadIdx.x * 4;   // 64 threads
    int beg = g_rowptr[v], end = g_rowptr[v + 1];
    float ax = 0.f, ay = 0.f, az = 0.f, aw = 0.f;
    int p = beg;
    for (; p + 1 < end; p += 2) {
        int s0 = g_csrsrc[p], s1 = g_csrsrc[p + 1];
        float4 v0 = *reinterpret_cast<const float4*>(hv + (size_t)s0 * H + c);
        float4 v1 = *reinterpret_cast<const float4*>(hv + (size_t)s1 * H + c);
        ax += v0.x + v1.x; ay += v0.y + v1.y; az += v0.z + v1.z; aw += v0.w + v1.w;
    }
    if (p < end) {
        int s0 = g_csrsrc[p];
        float4 v0 = *reinterpret_cast<const float4*>(hv + (size_t)s0 * H + c);
        ax += v0.x; ay += v0.y; az += v0.z; aw += v0.w;
    }
    __nv_bfloat16 hx = __float2bfloat16(ax), hy = __float2bfloat16(ay);
    __nv_bfloat16 hz = __float2bfloat16(az), hw = __float2bfloat16(aw);
    __nv_bfloat16 lx = __float2bfloat16(ax - __bfloat162float(hx));
    __nv_bfloat16 ly = __float2bfloat16(ay - __bfloat162float(hy));
    __nv_bfloat16 lz = __float2bfloat16(az - __bfloat162float(hz));
    __nv_bfloat16 lw = __float2bfloat16(aw - __bfloat162float(hw));
    size_t off = (size_t)v * H + c;
    *reinterpret_cast<__nv_bfloat162*>(&g_Tb_hi[off])     = __nv_bfloat162(hx, hy);
    *reinterpret_cast<__nv_bfloat162*>(&g_Tb_hi[off + 2]) = __nv_bfloat162(hz, hw);
    *reinterpret_cast<__nv_bfloat162*>(&g_Tb_lo[off])     = __nv_bfloat162(lx, ly);
    *reinterpret_cast<__nv_bfloat162*>(&g_Tb_lo[off + 2]) = __nv_bfloat162(lz, lw);
}

// ------------------------- fused GRU (+ final-round score & gate fusion) ----------
// Grid covers rows exactly: N_NODES*(H/4) = 1,280,000 = 5000 blocks * 256 (no partial
// block), so __syncthreads below is safe for all threads.
template <bool WRITE_SPLIT, bool FINAL>
__global__ void gru2_kernel(const float* __restrict__ hv_in, float* __restrict__ hv_out,
                            const float* __restrict__ cb, const float* __restrict__ cw,
                            const float* __restrict__ b_ih, const float* __restrict__ b_hh,
                            const float* __restrict__ dw,
                            const int* __restrict__ ntype,
                            const float* __restrict__ gate_w,
                            const float* __restrict__ gate_b) {
    __shared__ float spart[8];
    __shared__ float spartG[8];
    __shared__ float sgrow[4];
    __shared__ float sacc[NT * H];
    int idx = blockIdx.x * blockDim.x + threadIdx.x;
    if (idx >= N_NODES * (H / 4)) return;
    int n = idx / (H / 4);
    int c = (idx % (H / 4)) * 4;
    float deg = (float)(g_rowptr[n + 1] - g_rowptr[n]);
    float sh = g_sumhe[n];
    const float* G1 = g_G1 + (size_t)n * 1536;
    const float* V = g_V + (size_t)n * TH;
#define LD4(p) (*reinterpret_cast<const float4*>(p))
    float4 Ur = LD4(G1 + c),        Uz = LD4(G1 + 256 + c),  Un = LD4(G1 + 512 + c);
    float4 Hr = LD4(G1 + 768 + c),  Hz = LD4(G1 + 1024 + c), Hn = LD4(G1 + 1280 + c);
    float4 Vr = LD4(V + c),         Vz = LD4(V + 256 + c),   Vn = LD4(V + 512 + c);
    float4 cbr = LD4(cb + c), cbz = LD4(cb + 256 + c), cbn = LD4(cb + 512 + c);
    float4 cwr = LD4(cw + c), cwz = LD4(cw + 256 + c), cwn = LD4(cw + 512 + c);
    float4 bir = LD4(b_ih + c), biz = LD4(b_ih + 256 + c), bin_ = LD4(b_ih + 512 + c);
    float4 bhr = LD4(b_hh + c), bhz = LD4(b_hh + 256 + c), bhn = LD4(b_hh + 512 + c);
    float4 hc = LD4(hv_in + (size_t)n * H + c);
#undef LD4
    float4 o;
#define GRU1(X) { \
    float gir = deg * (Ur.X + cbr.X) + Vr.X + sh * cwr.X + bir.X; \
    float giz = deg * (Uz.X + cbz.X) + Vz.X + sh * cwz.X + biz.X; \
    float gin = deg * (Un.X + cbn.X) + Vn.X + sh * cwn.X + bin_.X; \
    float rr = 1.f / (1.f + expf(-(gir + Hr.X + bhr.X))); \
    float zz = 1.f / (1.f + expf(-(giz + Hz.X + bhz.X))); \
    float nn = tanhf(gin + rr * (Hn.X + bhn.X)); \
    o.X = (1.f - zz) * nn + zz * hc.X; }
    GRU1(x) GRU1(y) GRU1(z) GRU1(w)
#undef GRU1
    *reinterpret_cast<float4*>(hv_out + (size_t)n * H + c) = o;
    if (WRITE_SPLIT) {
        __nv_bfloat16 hx = __float2bfloat16(o.x), hy = __float2bfloat16(o.y);
        __nv_bfloat16 hz_ = __float2bfloat16(o.z), hw = __float2bfloat16(o.w);
        __nv_bfloat16 lx = __float2bfloat16(o.x - __bfloat162float(hx));
        __nv_bfloat16 ly = __float2bfloat16(o.y - __bfloat162float(hy));
        __nv_bfloat16 lz = __float2bfloat16(o.z - __bfloat162float(hz_));
        __nv_bfloat16 lw = __float2bfloat16(o.w - __bfloat162float(hw));
        size_t boff = (size_t)n * H + c;
        *reinterpret_cast<__nv_bfloat162*>(&g_hvb_hi[boff])     = __nv_bfloat162(hx, hy);
        *reinterpret_cast<__nv_bfloat162*>(&g_hvb_hi[boff + 2]) = __nv_bfloat162(hz_, hw);
        *reinterpret_cast<__nv_bfloat162*>(&g_hvb_lo[boff])     = __nv_bfloat162(lx, ly);
        *reinterpret_cast<__nv_bfloat162*>(&g_hvb_lo[boff + 2]) = __nv_bfloat162(lz, lw);
    }
    if (FINAL) {
        const int wid = threadIdx.x >> 5;
        const int rowb = threadIdx.x >> 6;      // row within block (0..3)
        // --- dest score dot (cst term cancels in log_softmax) ---
        float s = o.x * dw[c] + o.y * dw[c + 1] + o.z * dw[c + 2] + o.w * dw[c + 3];
        s = warp_sum(s);
        if ((threadIdx.x & 31) == 0) spart[wid] = s;
        // --- gate dot ---
        for (int i = threadIdx.x; i < NT * H; i += 256) sacc[i] = 0.f;
        int t = __ldg(&ntype[n]);
        const float* gw = gate_w + t * H;
        float d = o.x * gw[c] + o.y * gw[c + 1] + o.z * gw[c + 2] + o.w * gw[c + 3];
        d = warp_sum(d);
        if ((threadIdx.x & 31) == 0) spartG[wid] = d;
        __syncthreads();
        if ((threadIdx.x & 63) == 0) {
            if (n < N_NODES - 1)
                g_scores[n] = spart[rowb * 2] + spart[rowb * 2 + 1];
            float dot = spartG[rowb * 2] + spartG[rowb * 2 + 1];
            float g = 1.f / (1.f + expf(-(dot + gate_b[t])));
            sgrow[rowb] = g;
            atomicAdd(&g_gsum[t], g);
        }
        __syncthreads();
        float g = sgrow[rowb];
        atomicAdd(&sacc[t * H + c],     g * o.x);
        atomicAdd(&sacc[t * H + c + 1], g * o.y);
        atomicAdd(&sacc[t * H + c + 2], g * o.z);
        atomicAdd(&sacc[t * H + c + 3], g * o.w);
        __syncthreads();
        for (int i = threadIdx.x; i < NT * H; i += 256) {
            float v = sacc[i];
            if (v != 0.f) atomicAdd(&g_accv[i], v);
        }
    }
}

// ------------------------- graph embed (two-phase) -------------------------
__global__ void gembed_part_kernel(const float* __restrict__ tog_w) {
    int c = blockIdx.x * 128 + threadIdx.x;
    int t = blockIdx.y;
    const float* W = tog_w + (size_t)t * H * GH;
    const float* av = g_accv + t * H;
    float acc = 0.f;
#pragma unroll 4
    for (int k = 0; k < H; k++) acc += av[k] * W[(size_t)k * GH + c];
    g_gpart[t * GH + c] = acc;
}

__global__ void gembed_final_kernel(const float* __restrict__ tog_b, float* __restrict__ outg) {
    int c = threadIdx.x;  // 512
    float acc = 0.f;
#pragma unroll
    for (int t = 0; t < NT; t++)
        acc += g_gpart[t * GH + c] + g_gsum[t] * tog_b[t * GH + c];
    outg[c] = acc;
}

// ------------------------- merged tail heads -------------------------
__global__ void heads_kernel(const float* __restrict__ ge, const float* __restrict__ hv,
                             const float* __restrict__ addn_w, const float* __restrict__ addn_b,
                             const float* __restrict__ nte, const float* __restrict__ init_w,
                             const float* __restrict__ init_b,
                             const float* __restrict__ adde_w, const float* __restrict__ adde_b,
                             float* __restrict__ out) {
    int tid = threadIdx.x;
    if (blockIdx.x == 0) {
        __shared__ float logits[4];
        if (tid < 128) {
            int t = tid >> 5, lane = tid & 31;
            float dot = 0.f;
            for (int k = lane; k < GH; k += 32) dot += ge[k] * addn_w[k * 4 + t];
            dot = warp_sum(dot);
            if (lane == 0) logits[t] = dot + addn_b[t];
        }
        __syncthreads();
        if (tid == 0) {
            float m = fmaxf(fmaxf(logits[0], logits[1]), fmaxf(logits[2], logits[3]));
            float s = 0.f;
            for (int i = 0; i < 4; i++) s += expf(logits[i] - m);
            float l = logf(s);
            for (int i = 0; i < 4; i++) out[OFF_NLOGP + i] = logits[i] - m - l;
        }
    } else if (blockIdx.x == 1) {
        int c = tid;
        float a0 = init_b[c], a1 = 0.f, a2 = 0.f, a3 = 0.f;
#pragma unroll 4
        for (int k = 0; k < H; k += 4) {
            a0 += nte[k] * init_w[(size_t)k * H + c];
            a1 += nte[k + 1] * init_w[(size_t)(k + 1) * H + c];
            a2 += nte[k + 2] * init_w[(size_t)(k + 2) * H + c];
            a3 += nte[k + 3] * init_w[(size_t)(k + 3) * H + c];
        }
#pragma unroll 4
        for (int k = 0; k < GH; k += 4) {
            a0 += ge[k] * init_w[(size_t)(H + k) * H + c];
            a1 += ge[k + 1] * init_w[(size_t)(H + k + 1) * H + c];
            a2 += ge[k + 2] * init_w[(size_t)(H + k + 2) * H + c];
            a3 += ge[k + 3] * init_w[(size_t)(H + k + 3) * H + c];
        }
        out[OFF_HVINIT + c] = a0 + a1 + a2 + a3;
    } else {
        if (tid < 32) {
            const float* se = hv + (size_t)(N_NODES - 1) * H;
            float dot = 0.f;
            for (int k = tid; k < GH; k += 32) dot += ge[k] * adde_w[k];
            for (int k = tid; k < H; k += 32) dot += se[k] * adde_w[GH + k];
            dot = warp_sum(dot);
            if (tid == 0) out[OFF_EDGE] = dot + adde_b[0];
        }
    }
}

// ------------------------- dest logsoftmax -------------------------
__global__ void destreduce_kernel() {
    __shared__ float s[1024];
    int tid = threadIdx.x;
    float m = -INFINITY;
    for (int i = tid; i < N_NODES - 1; i += 1024) m = fmaxf(m, g_scores[i]);
    s[tid] = m; __syncthreads();
    for (int d = 512; d; d >>= 1) {
        if (tid < d) s[tid] = fmaxf(s[tid], s[tid + d]);
        __syncthreads();
    }
    float M = s[0];
    __syncthreads();
    float sum = 0.f;
    for (int i = tid; i < N_NODES - 1; i += 1024) sum += expf(g_scores[i] - M);
    s[tid] = sum; __syncthreads();
    for (int d = 512; d; d >>= 1) {
        if (tid < d) s[tid] += s[tid + d];
        __syncthreads();
    }
    if (tid == 0) { g_red[0] = M; g_red[1] = logf(s[0]); }
}

__global__ void destwrite_kernel(float* __restrict__ out) {
    int i = blockIdx.x * blockDim.x + threadIdx.x;
    if (i < N_NODES - 1) out[i] = g_scores[i] - g_red[0] - g_red[1];
}

// ------------------------- host -------------------------
extern "C" void kernel_launch(void* const* d_in, const int* in_sizes, int n_in,
                              void* d_out, int out_size) {
    const float* hv0   = (const float*)d_in[0];
    const float* he    = (const float*)d_in[1];
    const int*   ntype = (const int*)d_in[2];
    const int*   src   = (const int*)d_in[3];
    const int*   dst   = (const int*)d_in[4];
    const float* msg_w = (const float*)d_in[5];
    const float* msg_b = (const float*)d_in[6];
    const float* w_ih  = (const float*)d_in[7];
    const float* b_ih  = (const float*)d_in[8];
    const float* w_hh  = (const float*)d_in[9];
    const float* b_hh  = (const float*)d_in[10];
    const float* gate_w = (const float*)d_in[11];
    const float* gate_b = (const float*)d_in[12];
    const float* tog_w  = (const float*)d_in[13];
    const float* tog_b  = (const float*)d_in[14];
    const float* addn_w = (const float*)d_in[15];
    const float* addn_b = (const float*)d_in[16];
    const float* nte    = (const float*)d_in[17];
    const float* init_w = (const float*)d_in[18];
    const float* init_b = (const float*)d_in[19];
    const float* adde_w = (const float*)d_in[20];
    const float* adde_b = (const float*)d_in[21];
    const float* dest_w = (const float*)d_in[22];
    const float* dest_b = (const float*)d_in[23];
    float* out = (float*)d_out;

    void *p;
    cudaGetSymbolAddress(&p, g_G1);      float* G1 = (float*)p;
    cudaGetSymbolAddress(&p, g_V);       float* V = (float*)p;
    cudaGetSymbolAddress(&p, g_hv1);     float* Hv1 = (float*)p;
    cudaGetSymbolAddress(&p, g_cb);      float* Cb = (float*)p;
    cudaGetSymbolAddress(&p, g_cw);      float* Cw = (float*)p;
    cudaGetSymbolAddress(&p, g_hvb_hi);  __nv_bfloat16* HvHi = (__nv_bfloat16*)p;
    cudaGetSymbolAddress(&p, g_hvb_lo);  __nv_bfloat16* HvLo = (__nv_bfloat16*)p;
    cudaGetSymbolAddress(&p, g_Tb_hi);   __nv_bfloat16* TbHi = (__nv_bfloat16*)p;
    cudaGetSymbolAddress(&p, g_Tb_lo);   __nv_bfloat16* TbLo = (__nv_bfloat16*)p;
    cudaGetSymbolAddress(&p, g_B1_hi);   __nv_bfloat16* B1Hi = (__nv_bfloat16*)p;
    cudaGetSymbolAddress(&p, g_B1_lo);   __nv_bfloat16* B1Lo = (__nv_bfloat16*)p;
    cudaGetSymbolAddress(&p, g_B2_hi);   __nv_bfloat16* B2Hi = (__nv_bfloat16*)p;
    cudaGetSymbolAddress(&p, g_B2_lo);   __nv_bfloat16* B2Lo = (__nv_bfloat16*)p;

    // Streams/events created ONCE on the first (uncaptured) call, reused after.
    static cudaStream_t sA = nullptr, sB = nullptr;
    static cudaEvent_t evFork, evPrep, evCbcw, evT0, evV0, evG, evV1, evTail, evD;
    static bool s_init = false;
    if (!s_init) {
        cudaStreamCreateWithFlags(&sA, cudaStreamNonBlocking);
        cudaStreamCreateWithFlags(&sB, cudaStreamNonBlocking);
        cudaEventCreateWithFlags(&evFork, cudaEventDisableTiming);
        cudaEventCreateWithFlags(&evPrep, cudaEventDisableTiming);
        cudaEventCreateWithFlags(&evCbcw, cudaEventDisableTiming);
        cudaEventCreateWithFlags(&evT0,   cudaEventDisableTiming);
        cudaEventCreateWithFlags(&evV0,   cudaEventDisableTiming);
        cudaEventCreateWithFlags(&evG,    cudaEventDisableTiming);
        cudaEventCreateWithFlags(&evV1,   cudaEventDisableTiming);
        cudaEventCreateWithFlags(&evTail, cudaEventDisableTiming);
        cudaEventCreateWithFlags(&evD,    cudaEventDisableTiming);
        cudaFuncSetAttribute(mma_gemm_dual_kernel,
                             cudaFuncAttributeMaxDynamicSharedMemorySize, GEMM_SMEM);
        cudaFuncSetAttribute(mma_gemm_batch_kernel,
                             cudaFuncAttributeMaxDynamicSharedMemorySize, GEMM_SMEM);
        s_init = true;
    }

    const int MT = (N_NODES + 127) / 128;  // 157

    // ---- fork prep branch onto sB: hv0 split + weight splits + batch GEMM ----
    cudaEventRecord(evFork, 0);
    cudaStreamWaitEvent(sB, evFork, 0);
    split_kernel<<<(N_NODES * H + 255) / 256, 256, 0, sB>>>(hv0, HvHi, HvLo, N_NODES * H);
    {
        const int total = 2 * (GH * GH) + 2 * (TH * GH) + 2 * (TH * H);
        prep_split_kernel<<<(total + 255) / 256, 256, 0, sB>>>(msg_w, w_ih, w_hh);
    }
    mma_gemm_batch_kernel<<<dim3(H / 128, TH / 128, 4), 256, GEMM_SMEM, sB>>>();
    cudaEventRecord(evPrep, sB);                 // gates round GEMMs (B1/B2 ready)
    cbcw_kernel<<<(2 * TH + 7) / 8, 256, 0, sB>>>(msg_w, msg_b, w_ih);
    cudaEventRecord(evCbcw, sB);                 // gates gru2 only (cb/cw ready)

    // ---- main: CSR build ----
    init_kernel<<<(N_NODES + 255) / 256, 256>>>();
    deg_kernel<<<(N_EDGES + 255) / 256, 256>>>(dst, he);
    scan_kernel<<<1, 1024>>>();
    scatter_kernel<<<(N_EDGES + 255) / 256, 256>>>(src, dst);
    cudaEventRecord(evT0, 0);

    // ---- round 0 ----
    {
        const __nv_bfloat16 *b1h = B1Hi, *b1l = B1Lo, *b2h = B2Hi, *b2l = B2Lo;
        cudaStreamWaitEvent(sA, evT0, 0);
        taggr_kernel<<<N_NODES, 64, 0, sA>>>(hv0);
        cudaStreamWaitEvent(sA, evPrep, 0);
        mma_gemm_dual_kernel<<<dim3(6, MT), 256, GEMM_SMEM, sA>>>(
            HvHi, HvLo, TbHi, TbLo, b1h, b1l, b2h, b2l, G1, V, 12);
        cudaEventRecord(evV0, sA);
        cudaStreamWaitEvent(0, evPrep, 0);
        mma_gemm_dual_kernel<<<dim3(12, MT), 256, GEMM_SMEM>>>(
            HvHi, HvLo, TbHi, TbLo, b1h, b1l, b2h, b2l, G1, V, 0);
        cudaStreamWaitEvent(0, evV0, 0);
        cudaStreamWaitEvent(0, evCbcw, 0);
        gru2_kernel<true, false><<<(N_NODES * (H / 4) + 255) / 256, 256>>>(
            hv0, Hv1, Cb, Cw, b_ih, b_hh, dest_w, ntype, gate_w, gate_b);
        cudaEventRecord(evG, 0);
    }

    // ---- round 1 (final: gru fuses dest-score + gate accumulation) ----
    {
        const __nv_bfloat16 *b1h = B1Hi + (size_t)1536 * H, *b1l = B1Lo + (size_t)1536 * H;
        const __nv_bfloat16 *b2h = B2Hi + (size_t)TH * H,   *b2l = B2Lo + (size_t)TH * H;
        cudaStreamWaitEvent(sA, evG, 0);
        taggr_kernel<<<N_NODES, 64, 0, sA>>>(Hv1);
        mma_gemm_dual_kernel<<<dim3(6, MT), 256, GEMM_SMEM, sA>>>(
            HvHi, HvLo, TbHi, TbLo, b1h, b1l, b2h, b2l, G1, V, 12);
        cudaEventRecord(evV1, sA);
        mma_gemm_dual_kernel<<<dim3(12, MT), 256, GEMM_SMEM>>>(
            HvHi, HvLo, TbHi, TbLo, b1h, b1l, b2h, b2l, G1, V, 0);
        cudaStreamWaitEvent(0, evV1, 0);
        gru2_kernel<false, true><<<(N_NODES * (H / 4) + 255) / 256, 256>>>(
            Hv1, out, Cb + TH, Cw + TH, b_ih + TH, b_hh + TH, dest_w, ntype, gate_w, gate_b);
        cudaEventRecord(evTail, 0);
    }

    // ---- tail: dest logsoftmax on sA, embed chain on main ----
    cudaStreamWaitEvent(sA, evTail, 0);
    destreduce_kernel<<<1, 1024, 0, sA>>>();
    destwrite_kernel<<<(N_NODES - 1 + 255) / 256, 256, 0, sA>>>(out + OFF_DEST);
    cudaEventRecord(evD, sA);

    gembed_part_kernel<<<dim3(GH / 128, NT), 128>>>(tog_w);
    gembed_final_kernel<<<1, 512>>>(tog_b, out + OFF_GEMB);
    heads_kernel<<<3, 256>>>(out + OFF_GEMB, out, addn_w, addn_b,
                             nte, init_w, init_b, adde_w, adde_b, out);

    // join everything back to the main stream before capture ends
    cudaStreamWaitEvent(0, evD, 0);
}

// round 16
// speedup vs baseline: 1.1619x; 1.0320x over previous
#include <cuda_runtime.h>
#include <cuda_bf16.h>
#include <math.h>
#include <stdint.h>

#define N_NODES 20000
#define N_EDGES 320000
#define H 256
#define GH 512
#define TH 768
#define NT 3

#define OFF_GEMB   5120000
#define OFF_NLOGP  5120512
#define OFF_HVINIT 5120516
#define OFF_EDGE   5120772
#define OFF_DEST   5120773

// M-half split (y-tiles / rows)
#define Y_H0 79
#define Y_H1 78
#define ROWS_H0 10112
#define ROWS_H1 (N_NODES - ROWS_H0)

// ------------------------- scratch -------------------------
__device__ __align__(16) float g_G1[N_NODES * 1536];
__device__ __align__(16) float g_V[N_NODES * TH];
__device__ __align__(16) float g_hv1[N_NODES * H];
__device__ __align__(16) float g_cb[2 * TH];
__device__ __align__(16) float g_cw[2 * TH];
__device__ int   g_deg[N_NODES];
__device__ float g_sumhe[N_NODES];
__device__ int   g_rowptr[N_NODES + 1];
__device__ int   g_cursor[N_NODES];
__device__ int   g_csrsrc[N_EDGES];
__device__ float g_accv[NT * H];
__device__ float g_gsum[NT];
__device__ float g_gpart[NT * GH];
__device__ float g_scores[N_NODES];
__device__ float g_red[4];

__device__ __align__(16) __nv_bfloat16 g_hvb_hi[N_NODES * H];
__device__ __align__(16) __nv_bfloat16 g_hvb_lo[N_NODES * H];
__device__ __align__(16) __nv_bfloat16 g_Tb_hi[N_NODES * H];
__device__ __align__(16) __nv_bfloat16 g_Tb_lo[N_NODES * H];
__device__ __align__(16) __nv_bfloat16 g_Wih_hi[2 * TH * GH];
__device__ __align__(16) __nv_bfloat16 g_Wih_lo[2 * TH * GH];
__device__ __align__(16) __nv_bfloat16 g_ms_hi[2 * GH * GH];
__device__ __align__(16) __nv_bfloat16 g_ms_lo[2 * GH * GH];
__device__ __align__(16) __nv_bfloat16 g_B1_hi[2 * 1536 * H];
__device__ __align__(16) __nv_bfloat16 g_B1_lo[2 * 1536 * H];
__device__ __align__(16) __nv_bfloat16 g_B2_hi[2 * TH * H];
__device__ __align__(16) __nv_bfloat16 g_B2_lo[2 * TH * H];

__device__ __forceinline__ float warp_sum(float v) {
#pragma unroll
    for (int o = 16; o; o >>= 1) v += __shfl_xor_sync(0xffffffffu, v, o);
    return v;
}

__device__ __forceinline__ uint32_t smem_u32(const void* p) {
    uint32_t a;
    asm("{ .reg .u64 t; cvta.to.shared.u64 t, %1; cvt.u32.u64 %0, t; }" : "=r"(a) : "l"(p));
    return a;
}

// ------------------------- tensor macros -------------------------
#define CP_ASYNC(dst, src, sz) \
    asm volatile("cp.async.ca.shared.global [%0], [%1], 16, %2;" \
                 :: "r"(dst), "l"(src), "r"(sz) : "memory")
#define CP_COMMIT()  asm volatile("cp.async.commit_group;" ::: "memory")
#define CP_WAIT0()   asm volatile("cp.async.wait_group 0;" ::: "memory")

#define LDSM4(r, a) \
    asm volatile("ldmatrix.sync.aligned.m8n8.x4.shared.b16 {%0,%1,%2,%3}, [%4];" \
                 : "=r"((r)[0]), "=r"((r)[1]), "=r"((r)[2]), "=r"((r)[3]) : "r"(a))
#define LDSM2(r, a) \
    asm volatile("ldmatrix.sync.aligned.m8n8.x2.shared.b16 {%0,%1}, [%2];" \
                 : "=r"((r)[0]), "=r"((r)[1]) : "r"(a))
#define MMA_BF16(c, a, b) \
    asm volatile("mma.sync.aligned.m16n8k16.row.col.f32.bf16.bf16.f32 " \
                 "{%0,%1,%2,%3}, {%4,%5,%6,%7}, {%8,%9}, {%0,%1,%2,%3};" \
                 : "+f"((c)[0]), "+f"((c)[1]), "+f"((c)[2]), "+f"((c)[3]) \
                 : "r"((a)[0]), "r"((a)[1]), "r"((a)[2]), "r"((a)[3]), \
                   "r"((b)[0]), "r"((b)[1]))

// ------------------------- bf16 split (hv0 only) -------------------------
__global__ void split_kernel(const float* __restrict__ in,
                             __nv_bfloat16* __restrict__ hi,
                             __nv_bfloat16* __restrict__ lo, int n) {
    int i = blockIdx.x * blockDim.x + threadIdx.x;
    if (i < n) {
        float x = in[i];
        __nv_bfloat16 h = __float2bfloat16(x);
        float r = x - __bfloat162float(h);
        hi[i] = h;
        lo[i] = __float2bfloat16(r);
    }
}

// merged weight-split prep (one launch)
__global__ void prep_split_kernel(const float* __restrict__ msg_w,
                                  const float* __restrict__ w_ih,
                                  const float* __restrict__ w_hh) {
    const int nMS = GH * GH, nWI = TH * GH, nWH = TH * H;
    int i = blockIdx.x * blockDim.x + threadIdx.x;
    float x;
    __nv_bfloat16 *dh, *dl;
    if (i < 2 * nMS) {
        int t = i / nMS, k = i % nMS;
        x = msg_w[(size_t)t * (2 * H + 1) * GH + k];
        dh = g_ms_hi + i; dl = g_ms_lo + i;
    } else if (i < 2 * nMS + 2 * nWI) {
        int j = i - 2 * nMS;
        x = w_ih[j];
        dh = g_Wih_hi + j; dl = g_Wih_lo + j;
    } else if (i < 2 * nMS + 2 * nWI + 2 * nWH) {
        int j = i - 2 * nMS - 2 * nWI;
        int t = j / nWH, k = j % nWH;
        x = w_hh[j];
        size_t off = (size_t)t * 1536 * H + (size_t)TH * H + k;
        dh = g_B1_hi + off; dl = g_B1_lo + off;
    } else return;
    __nv_bfloat16 h = __float2bfloat16(x);
    *dh = h;
    *dl = __float2bfloat16(x - __bfloat162float(h));
}

// ------------------------- mma.sync bf16x3 GEMM core -------------------------
#define GEMM_SMEM 81920

template <bool BF16OUT>
__device__ __forceinline__ void gemm_core(
    const __nv_bfloat16* __restrict__ Ahi, const __nv_bfloat16* __restrict__ Alo,
    const __nv_bfloat16* __restrict__ Bhi, const __nv_bfloat16* __restrict__ Blo,
    float* __restrict__ C, __nv_bfloat16* __restrict__ Dhi, __nv_bfloat16* __restrict__ Dlo,
    int M, int Np, int K, int bm, int bn, char* smem)
{
    const int tid = threadIdx.x;
    const int wid = tid >> 5, lane = tid & 31;
    const int wm = wid & 1, wn = wid >> 1;
    const uint32_t sbase = smem_u32(smem);

    float acc[4][4][4];
#pragma unroll
    for (int i = 0; i < 4; i++)
#pragma unroll
        for (int j = 0; j < 4; j++) {
            acc[i][j][0] = 0.f; acc[i][j][1] = 0.f;
            acc[i][j][2] = 0.f; acc[i][j][3] = 0.f;
        }

    const int nch = K / 32;

    auto load_stage = [&](int s, int k0) {
        uint32_t st = sbase + s * 40960;
#pragma unroll
        for (int it = 0; it < 2; it++) {
            int u = tid + it * 256;
            int row = u >> 2, g = u & 3;
            uint32_t d = st + row * 80 + g * 16;
            int gr = bm + row;
            size_t aoff = (size_t)(gr < M ? gr : 0) * K + k0 + g * 8;
            uint32_t asz = (gr < M) ? 16u : 0u;
            CP_ASYNC(d,         Ahi + aoff, asz);
            CP_ASYNC(d + 10240, Alo + aoff, asz);
            size_t boff = (size_t)(bn + row) * K + k0 + g * 8;
            CP_ASYNC(d + 20480, Bhi + boff, 16u);
            CP_ASYNC(d + 30720, Blo + boff, 16u);
        }
    };

    load_stage(0, 0);
    CP_COMMIT();

    for (int c = 0; c < nch; c++) {
        CP_WAIT0();
        __syncthreads();
        if (c + 1 < nch) { load_stage((c + 1) & 1, (c + 1) * 32); CP_COMMIT(); }

        uint32_t st = sbase + (c & 1) * 40960;
#pragma unroll
        for (int ks = 0; ks < 2; ks++) {
            uint32_t ah[4][4], al[4][4], bh[4][2], bl[4][2];
#pragma unroll
            for (int mt = 0; mt < 4; mt++) {
                uint32_t addr = st + (uint32_t)(wm * 64 + mt * 16 + (lane & 15)) * 80
                              + ((lane >> 4) * 16) + ks * 32;
                LDSM4(ah[mt], addr);
                LDSM4(al[mt], addr + 10240);
            }
#pragma unroll
            for (int nt = 0; nt < 4; nt++) {
                uint32_t addr = st + 20480 + (uint32_t)(wn * 32 + nt * 8 + (lane & 7)) * 80
                              + (((lane >> 3) & 1) * 16) + ks * 32;
                LDSM2(bh[nt], addr);
                LDSM2(bl[nt], addr + 10240);
            }
#pragma unroll
            for (int mt = 0; mt < 4; mt++)
#pragma unroll
                for (int nt = 0; nt < 4; nt++) {
                    MMA_BF16(acc[mt][nt], ah[mt], bh[nt]);
                    MMA_BF16(acc[mt][nt], al[mt], bh[nt]);
                    MMA_BF16(acc[mt][nt], ah[mt], bl[nt]);
                }
        }
    }

#pragma unroll
    for (int mt = 0; mt < 4; mt++) {
        int r0 = bm + wm * 64 + mt * 16 + (lane >> 2);
#pragma unroll
        for (int nt = 0; nt < 4; nt++) {
            int col = bn + wn * 32 + nt * 8 + (lane & 3) * 2;
            if (BF16OUT) {
#pragma unroll
                for (int hh = 0; hh < 2; hh++) {
                    int r = r0 + hh * 8;
                    if (r < M) {
                        float vx = acc[mt][nt][hh * 2], vy = acc[mt][nt][hh * 2 + 1];
                        __nv_bfloat16 hx = __float2bfloat16(vx);
                        __nv_bfloat16 hy = __float2bfloat16(vy);
                        __nv_bfloat16 lx = __float2bfloat16(vx - __bfloat162float(hx));
                        __nv_bfloat16 ly = __float2bfloat16(vy - __bfloat162float(hy));
                        size_t o = (size_t)r * Np + col;
                        *reinterpret_cast<__nv_bfloat162*>(Dhi + o) = __nv_bfloat162(hx, hy);
                        *reinterpret_cast<__nv_bfloat162*>(Dlo + o) = __nv_bfloat162(lx, ly);
                    }
                }
            } else {
                if (r0 < M) {
                    float2 v; v.x = acc[mt][nt][0]; v.y = acc[mt][nt][1];
                    *reinterpret_cast<float2*>(C + (size_t)r0 * Np + col) = v;
                }
                if (r0 + 8 < M) {
                    float2 v; v.x = acc[mt][nt][2]; v.y = acc[mt][nt][3];
                    *reinterpret_cast<float2*>(C + (size_t)(r0 + 8) * Np + col) = v;
                }
            }
        }
    }
}

// per-round GEMM: z<12 -> G1 tile, z>=12 -> V tile; ybase selects M-half
__global__ void __launch_bounds__(256) mma_gemm_dual_kernel(
    const __nv_bfloat16* __restrict__ hvhi, const __nv_bfloat16* __restrict__ hvlo,
    const __nv_bfloat16* __restrict__ thi,  const __nv_bfloat16* __restrict__ tlo,
    const __nv_bfloat16* __restrict__ b1hi, const __nv_bfloat16* __restrict__ b1lo,
    const __nv_bfloat16* __restrict__ b2hi, const __nv_bfloat16* __restrict__ b2lo,
    float* __restrict__ G1, float* __restrict__ V, int z0, int ybase)
{
    extern __shared__ __align__(128) char smem[];
    int z = z0 + blockIdx.x;
    int bm = (ybase + blockIdx.y) * 128;
    if (z < 12)
        gemm_core<false>(hvhi, hvlo, b1hi, b1lo, G1, nullptr, nullptr,
                         N_NODES, 1536, H, bm, z * 128, smem);
    else
        gemm_core<false>(thi, tlo, b2hi, b2lo, V, nullptr, nullptr,
                         N_NODES, TH, H, bm, (z - 12) * 128, smem);
}

// batched small GEMM with bf16 hi/lo epilogue
__global__ void __launch_bounds__(256) mma_gemm_batch_kernel() {
    extern __shared__ __align__(128) char smem[];
    int z = blockIdx.z;
    int t = z >> 1, half = z & 1;
    __nv_bfloat16* Dhi = half ? (g_B2_hi + (size_t)t * TH * H)
                              : (g_B1_hi + (size_t)t * 1536 * H);
    __nv_bfloat16* Dlo = half ? (g_B2_lo + (size_t)t * TH * H)
                              : (g_B1_lo + (size_t)t * 1536 * H);
    gemm_core<true>(g_Wih_hi + (size_t)t * TH * GH, g_Wih_lo + (size_t)t * TH * GH,
                    g_ms_hi + (size_t)t * GH * GH + (size_t)half * H * GH,
                    g_ms_lo + (size_t)t * GH * GH + (size_t)half * H * GH,
                    nullptr, Dhi, Dlo, TH, H, GH,
                    blockIdx.y * 128, blockIdx.x * 128, smem);
}

// ------------------------- cb/cw precompute -------------------------
__global__ void cbcw_kernel(const float* __restrict__ msg_w, const float* __restrict__ msg_b,
                            const float* __restrict__ w_ih) {
    int g = blockIdx.x * 8 + (threadIdx.x >> 5);
    if (g >= 2 * TH) return;
    int t = g / TH, j = g % TH, lane = threadIdx.x & 31;
    const float* wr = w_ih + ((size_t)t * TH + j) * GH;
    const float* mb = msg_b + t * GH;
    const float* wh = msg_w + (size_t)t * (2 * H + 1) * GH + (size_t)(2 * H) * GH;
    float s1 = 0.f, s2 = 0.f;
    for (int c = lane; c < GH; c += 32) {
        float w = wr[c];
        s1 += mb[c] * w;
        s2 += wh[c] * w;
    }
    s1 = warp_sum(s1); s2 = warp_sum(s2);
    if (lane == 0) { g_cb[g] = s1; g_cw[g] = s2; }
}

// ------------------------- init / CSR build -------------------------
__global__ void init_kernel() {
    int i = blockIdx.x * blockDim.x + threadIdx.x;
    if (i < N_NODES) { g_deg[i] = 0; g_sumhe[i] = 0.f; g_cursor[i] = 0; }
    if (i < NT * H) g_accv[i] = 0.f;
    if (i < NT) g_gsum[i] = 0.f;
}

__global__ void deg_kernel(const int* __restrict__ dst, const float* __restrict__ he) {
    int e = blockIdx.x * blockDim.x + threadIdx.x;
    if (e < N_EDGES) {
        atomicAdd(&g_deg[dst[e]], 1);
        atomicAdd(&g_sumhe[dst[e]], he[e]);
    }
}

__global__ void scan_kernel() {
    __shared__ int s[1024];
    __shared__ int carry;
    if (threadIdx.x == 0) { carry = 0; g_rowptr[0] = 0; }
    __syncthreads();
    for (int base = 0; base < N_NODES; base += 8192) {
        int idx0 = base + threadIdx.x * 8;
        int v[8]; int sum = 0;
#pragma unroll
        for (int i = 0; i < 8; i++) {
            int ii = idx0 + i;
            v[i] = (ii < N_NODES) ? g_deg[ii] : 0;
            sum += v[i];
        }
        s[threadIdx.x] = sum;
        __syncthreads();
        for (int d = 1; d < 1024; d <<= 1) {
            int t = (threadIdx.x >= d) ? s[threadIdx.x - d] : 0;
            __syncthreads();
            s[threadIdx.x] += t;
            __syncthreads();
        }
        int run = s[threadIdx.x] - sum + carry;
#pragma unroll
        for (int i = 0; i < 8; i++) {
            int ii = idx0 + i;
            run += v[i];
            if (ii < N_NODES) g_rowptr[ii + 1] = run;
        }
        __syncthreads();
        if (threadIdx.x == 1023) carry += s[1023];
        __syncthreads();
    }
}

__global__ void scatter_kernel(const int* __restrict__ src, const int* __restrict__ dst) {
    int e = blockIdx.x * blockDim.x + threadIdx.x;
    if (e < N_EDGES) {
        int d = dst[e];
        int slot = atomicAdd(&g_cursor[d], 1);
        g_csrsrc[g_rowptr[d] + slot] = src[e];
    }
}

// ------------------------- T aggregation + fused bf16 split -------------------------
__global__ void taggr_kernel(const float* __restrict__ hv) {
    int v = blockIdx.x;
    int c = threadIdx.x * 4;   // 64 threads
    int beg = g_rowptr[v], end = g_rowptr[v + 1];
    float ax = 0.f, ay = 0.f, az = 0.f, aw = 0.f;
    int p = beg;
    for (; p + 1 < end; p += 2) {
        int s0 = g_csrsrc[p], s1 = g_csrsrc[p + 1];
        float4 v0 = *reinterpret_cast<const float4*>(hv + (size_t)s0 * H + c);
        float4 v1 = *reinterpret_cast<const float4*>(hv + (size_t)s1 * H + c);
        ax += v0.x + v1.x; ay += v0.y + v1.y; az += v0.z + v1.z; aw += v0.w + v1.w;
    }
    if (p < end) {
        int s0 = g_csrsrc[p];
        float4 v0 = *reinterpret_cast<const float4*>(hv + (size_t)s0 * H + c);
        ax += v0.x; ay += v0.y; az += v0.z; aw += v0.w;
    }
    __nv_bfloat16 hx = __float2bfloat16(ax), hy = __float2bfloat16(ay);
    __nv_bfloat16 hz = __float2bfloat16(az), hw = __float2bfloat16(aw);
    __nv_bfloat16 lx = __float2bfloat16(ax - __bfloat162float(hx));
    __nv_bfloat16 ly = __float2bfloat16(ay - __bfloat162float(hy));
    __nv_bfloat16 lz = __float2bfloat16(az - __bfloat162float(hz));
    __nv_bfloat16 lw = __float2bfloat16(aw - __bfloat162float(hw));
    size_t off = (size_t)v * H + c;
    *reinterpret_cast<__nv_bfloat162*>(&g_Tb_hi[off])     = __nv_bfloat162(hx, hy);
    *reinterpret_cast<__nv_bfloat162*>(&g_Tb_hi[off + 2]) = __nv_bfloat162(hz, hw);
    *reinterpret_cast<__nv_bfloat162*>(&g_Tb_lo[off])     = __nv_bfloat162(lx, ly);
    *reinterpret_cast<__nv_bfloat162*>(&g_Tb_lo[off + 2]) = __nv_bfloat162(lz, lw);
}

// ------------------------- fused GRU (row-ranged, + final-round score & gate) ------
// nrows is a multiple of 4 => full 256-thread blocks, __syncthreads safe.
template <bool WRITE_SPLIT, bool FINAL>
__global__ void gru2_kernel(const float* __restrict__ hv_in, float* __restrict__ hv_out,
                            const float* __restrict__ cb, const float* __restrict__ cw,
                            const float* __restrict__ b_ih, const float* __restrict__ b_hh,
                            const float* __restrict__ dw,
                            const int* __restrict__ ntype,
                            const float* __restrict__ gate_w,
                            const float* __restrict__ gate_b,
                            int row0, int nrows) {
    __shared__ float spart[8];
    __shared__ float spartG[8];
    __shared__ float sgrow[4];
    __shared__ float sacc[NT * H];
    int idx = blockIdx.x * blockDim.x + threadIdx.x;
    if (idx >= nrows * (H / 4)) return;
    int n = row0 + idx / (H / 4);
    int c = (idx % (H / 4)) * 4;
    float deg = (float)(g_rowptr[n + 1] - g_rowptr[n]);
    float sh = g_sumhe[n];
    const float* G1 = g_G1 + (size_t)n * 1536;
    const float* V = g_V + (size_t)n * TH;
#define LD4(p) (*reinterpret_cast<const float4*>(p))
    float4 Ur = LD4(G1 + c),        Uz = LD4(G1 + 256 + c),  Un = LD4(G1 + 512 + c);
    float4 Hr = LD4(G1 + 768 + c),  Hz = LD4(G1 + 1024 + c), Hn = LD4(G1 + 1280 + c);
    float4 Vr = LD4(V + c),         Vz = LD4(V + 256 + c),   Vn = LD4(V + 512 + c);
    float4 cbr = LD4(cb + c), cbz = LD4(cb + 256 + c), cbn = LD4(cb + 512 + c);
    float4 cwr = LD4(cw + c), cwz = LD4(cw + 256 + c), cwn = LD4(cw + 512 + c);
    float4 bir = LD4(b_ih + c), biz = LD4(b_ih + 256 + c), bin_ = LD4(b_ih + 512 + c);
    float4 bhr = LD4(b_hh + c), bhz = LD4(b_hh + 256 + c), bhn = LD4(b_hh + 512 + c);
    float4 hc = LD4(hv_in + (size_t)n * H + c);
#undef LD4
    float4 o;
#define GRU1(X) { \
    float gir = deg * (Ur.X + cbr.X) + Vr.X + sh * cwr.X + bir.X; \
    float giz = deg * (Uz.X + cbz.X) + Vz.X + sh * cwz.X + biz.X; \
    float gin = deg * (Un.X + cbn.X) + Vn.X + sh * cwn.X + bin_.X; \
    float rr = 1.f / (1.f + expf(-(gir + Hr.X + bhr.X))); \
    float zz = 1.f / (1.f + expf(-(giz + Hz.X + bhz.X))); \
    float nn = tanhf(gin + rr * (Hn.X + bhn.X)); \
    o.X = (1.f - zz) * nn + zz * hc.X; }
    GRU1(x) GRU1(y) GRU1(z) GRU1(w)
#undef GRU1
    *reinterpret_cast<float4*>(hv_out + (size_t)n * H + c) = o;
    if (WRITE_SPLIT) {
        __nv_bfloat16 hx = __float2bfloat16(o.x), hy = __float2bfloat16(o.y);
        __nv_bfloat16 hz_ = __float2bfloat16(o.z), hw = __float2bfloat16(o.w);
        __nv_bfloat16 lx = __float2bfloat16(o.x - __bfloat162float(hx));
        __nv_bfloat16 ly = __float2bfloat16(o.y - __bfloat162float(hy));
        __nv_bfloat16 lz = __float2bfloat16(o.z - __bfloat162float(hz_));
        __nv_bfloat16 lw = __float2bfloat16(o.w - __bfloat162float(hw));
        size_t boff = (size_t)n * H + c;
        *reinterpret_cast<__nv_bfloat162*>(&g_hvb_hi[boff])     = __nv_bfloat162(hx, hy);
        *reinterpret_cast<__nv_bfloat162*>(&g_hvb_hi[boff + 2]) = __nv_bfloat162(hz_, hw);
        *reinterpret_cast<__nv_bfloat162*>(&g_hvb_lo[boff])     = __nv_bfloat162(lx, ly);
        *reinterpret_cast<__nv_bfloat162*>(&g_hvb_lo[boff + 2]) = __nv_bfloat162(lz, lw);
    }
    if (FINAL) {
        const int wid = threadIdx.x >> 5;
        const int rowb = threadIdx.x >> 6;
        float s = o.x * dw[c] + o.y * dw[c + 1] + o.z * dw[c + 2] + o.w * dw[c + 3];
        s = warp_sum(s);
        if ((threadIdx.x & 31) == 0) spart[wid] = s;
        for (int i = threadIdx.x; i < NT * H; i += 256) sacc[i] = 0.f;
        int t = __ldg(&ntype[n]);
        const float* gw = gate_w + t * H;
        float d = o.x * gw[c] + o.y * gw[c + 1] + o.z * gw[c + 2] + o.w * gw[c + 3];
        d = warp_sum(d);
        if ((threadIdx.x & 31) == 0) spartG[wid] = d;
        __syncthreads();
        if ((threadIdx.x & 63) == 0) {
            if (n < N_NODES - 1)
                g_scores[n] = spart[rowb * 2] + spart[rowb * 2 + 1];
            float dot = spartG[rowb * 2] + spartG[rowb * 2 + 1];
            float g = 1.f / (1.f + expf(-(dot + gate_b[t])));
            sgrow[rowb] = g;
            atomicAdd(&g_gsum[t], g);
        }
        __syncthreads();
        float g = sgrow[rowb];
        atomicAdd(&sacc[t * H + c],     g * o.x);
        atomicAdd(&sacc[t * H + c + 1], g * o.y);
        atomicAdd(&sacc[t * H + c + 2], g * o.z);
        atomicAdd(&sacc[t * H + c + 3], g * o.w);
        __syncthreads();
        for (int i = threadIdx.x; i < NT * H; i += 256) {
            float v = sacc[i];
            if (v != 0.f) atomicAdd(&g_accv[i], v);
        }
    }
}

// ------------------------- graph embed (two-phase) -------------------------
__global__ void gembed_part_kernel(const float* __restrict__ tog_w) {
    int c = blockIdx.x * 128 + threadIdx.x;
    int t = blockIdx.y;
    const float* W = tog_w + (size_t)t * H * GH;
    const float* av = g_accv + t * H;
    float acc = 0.f;
#pragma unroll 4
    for (int k = 0; k < H; k++) acc += av[k] * W[(size_t)k * GH + c];
    g_gpart[t * GH + c] = acc;
}

__global__ void gembed_final_kernel(const float* __restrict__ tog_b, float* __restrict__ outg) {
    int c = threadIdx.x;  // 512
    float acc = 0.f;
#pragma unroll
    for (int t = 0; t < NT; t++)
        acc += g_gpart[t * GH + c] + g_gsum[t] * tog_b[t * GH + c];
    outg[c] = acc;
}

// ------------------------- merged tail heads -------------------------
__global__ void heads_kernel(const float* __restrict__ ge, const float* __restrict__ hv,
                             const float* __restrict__ addn_w, const float* __restrict__ addn_b,
                             const float* __restrict__ nte, const float* __restrict__ init_w,
                             const float* __restrict__ init_b,
                             const float* __restrict__ adde_w, const float* __restrict__ adde_b,
                             float* __restrict__ out) {
    int tid = threadIdx.x;
    if (blockIdx.x == 0) {
        __shared__ float logits[4];
        if (tid < 128) {
            int t = tid >> 5, lane = tid & 31;
            float dot = 0.f;
            for (int k = lane; k < GH; k += 32) dot += ge[k] * addn_w[k * 4 + t];
            dot = warp_sum(dot);
            if (lane == 0) logits[t] = dot + addn_b[t];
        }
        __syncthreads();
        if (tid == 0) {
            float m = fmaxf(fmaxf(logits[0], logits[1]), fmaxf(logits[2], logits[3]));
            float s = 0.f;
            for (int i = 0; i < 4; i++) s += expf(logits[i] - m);
            float l = logf(s);
            for (int i = 0; i < 4; i++) out[OFF_NLOGP + i] = logits[i] - m - l;
        }
    } else if (blockIdx.x == 1) {
        int c = tid;
        float a0 = init_b[c], a1 = 0.f, a2 = 0.f, a3 = 0.f;
#pragma unroll 4
        for (int k = 0; k < H; k += 4) {
            a0 += nte[k] * init_w[(size_t)k * H + c];
            a1 += nte[k + 1] * init_w[(size_t)(k + 1) * H + c];
            a2 += nte[k + 2] * init_w[(size_t)(k + 2) * H + c];
            a3 += nte[k + 3] * init_w[(size_t)(k + 3) * H + c];
        }
#pragma unroll 4
        for (int k = 0; k < GH; k += 4) {
            a0 += ge[k] * init_w[(size_t)(H + k) * H + c];
            a1 += ge[k + 1] * init_w[(size_t)(H + k + 1) * H + c];
            a2 += ge[k + 2] * init_w[(size_t)(H + k + 2) * H + c];
            a3 += ge[k + 3] * init_w[(size_t)(H + k + 3) * H + c];
        }
        out[OFF_HVINIT + c] = a0 + a1 + a2 + a3;
    } else {
        if (tid < 32) {
            const float* se = hv + (size_t)(N_NODES - 1) * H;
            float dot = 0.f;
            for (int k = tid; k < GH; k += 32) dot += ge[k] * adde_w[k];
            for (int k = tid; k < H; k += 32) dot += se[k] * adde_w[GH + k];
            dot = warp_sum(dot);
            if (tid == 0) out[OFF_EDGE] = dot + adde_b[0];
        }
    }
}

// ------------------------- dest logsoftmax -------------------------
__global__ void destreduce_kernel() {
    __shared__ float s[1024];
    int tid = threadIdx.x;
    float m = -INFINITY;
    for (int i = tid; i < N_NODES - 1; i += 1024) m = fmaxf(m, g_scores[i]);
    s[tid] = m; __syncthreads();
    for (int d = 512; d; d >>= 1) {
        if (tid < d) s[tid] = fmaxf(s[tid], s[tid + d]);
        __syncthreads();
    }
    float M = s[0];
    __syncthreads();
    float sum = 0.f;
    for (int i = tid; i < N_NODES - 1; i += 1024) sum += expf(g_scores[i] - M);
    s[tid] = sum; __syncthreads();
    for (int d = 512; d; d >>= 1) {
        if (tid < d) s[tid] += s[tid + d];
        __syncthreads();
    }
    if (tid == 0) { g_red[0] = M; g_red[1] = logf(s[0]); }
}

__global__ void destwrite_kernel(float* __restrict__ out) {
    int i = blockIdx.x * blockDim.x + threadIdx.x;
    if (i < N_NODES - 1) out[i] = g_scores[i] - g_red[0] - g_red[1];
}

// ------------------------- host -------------------------
extern "C" void kernel_launch(void* const* d_in, const int* in_sizes, int n_in,
                              void* d_out, int out_size) {
    const float* hv0   = (const float*)d_in[0];
    const float* he    = (const float*)d_in[1];
    const int*   ntype = (const int*)d_in[2];
    const int*   src   = (const int*)d_in[3];
    const int*   dst   = (const int*)d_in[4];
    const float* msg_w = (const float*)d_in[5];
    const float* msg_b = (const float*)d_in[6];
    const float* w_ih  = (const float*)d_in[7];
    const float* b_ih  = (const float*)d_in[8];
    const float* w_hh  = (const float*)d_in[9];
    const float* b_hh  = (const float*)d_in[10];
    const float* gate_w = (const float*)d_in[11];
    const float* gate_b = (const float*)d_in[12];
    const float* tog_w  = (const float*)d_in[13];
    const float* tog_b  = (const float*)d_in[14];
    const float* addn_w = (const float*)d_in[15];
    const float* addn_b = (const float*)d_in[16];
    const float* nte    = (const float*)d_in[17];
    const float* init_w = (const float*)d_in[18];
    const float* init_b = (const float*)d_in[19];
    const float* adde_w = (const float*)d_in[20];
    const float* adde_b = (const float*)d_in[21];
    const float* dest_w = (const float*)d_in[22];
    const float* dest_b = (const float*)d_in[23];
    float* out = (float*)d_out;

    void *p;
    cudaGetSymbolAddress(&p, g_G1);      float* G1 = (float*)p;
    cudaGetSymbolAddress(&p, g_V);       float* V = (float*)p;
    cudaGetSymbolAddress(&p, g_hv1);     float* Hv1 = (float*)p;
    cudaGetSymbolAddress(&p, g_cb);      float* Cb = (float*)p;
    cudaGetSymbolAddress(&p, g_cw);      float* Cw = (float*)p;
    cudaGetSymbolAddress(&p, g_hvb_hi);  __nv_bfloat16* HvHi = (__nv_bfloat16*)p;
    cudaGetSymbolAddress(&p, g_hvb_lo);  __nv_bfloat16* HvLo = (__nv_bfloat16*)p;
    cudaGetSymbolAddress(&p, g_Tb_hi);   __nv_bfloat16* TbHi = (__nv_bfloat16*)p;
    cudaGetSymbolAddress(&p, g_Tb_lo);   __nv_bfloat16* TbLo = (__nv_bfloat16*)p;
    cudaGetSymbolAddress(&p, g_B1_hi);   __nv_bfloat16* B1Hi = (__nv_bfloat16*)p;
    cudaGetSymbolAddress(&p, g_B1_lo);   __nv_bfloat16* B1Lo = (__nv_bfloat16*)p;
    cudaGetSymbolAddress(&p, g_B2_hi);   __nv_bfloat16* B2Hi = (__nv_bfloat16*)p;
    cudaGetSymbolAddress(&p, g_B2_lo);   __nv_bfloat16* B2Lo = (__nv_bfloat16*)p;

    // Streams/events created ONCE on the first (uncaptured) call, reused after.
    static cudaStream_t sA = nullptr, sB = nullptr;
    static cudaEvent_t evFork, evPrep, evCbcw, evT0, evD;
    static cudaEvent_t evG1h0[2], evG1h1[2], evVh0[2], evVh1[2], evGru[2];
    static bool s_init = false;
    if (!s_init) {
        cudaStreamCreateWithFlags(&sA, cudaStreamNonBlocking);
        cudaStreamCreateWithFlags(&sB, cudaStreamNonBlocking);
        cudaEventCreateWithFlags(&evFork, cudaEventDisableTiming);
        cudaEventCreateWithFlags(&evPrep, cudaEventDisableTiming);
        cudaEventCreateWithFlags(&evCbcw, cudaEventDisableTiming);
        cudaEventCreateWithFlags(&evT0,   cudaEventDisableTiming);
        cudaEventCreateWithFlags(&evD,    cudaEventDisableTiming);
        for (int r = 0; r < 2; r++) {
            cudaEventCreateWithFlags(&evG1h0[r], cudaEventDisableTiming);
            cudaEventCreateWithFlags(&evG1h1[r], cudaEventDisableTiming);
            cudaEventCreateWithFlags(&evVh0[r],  cudaEventDisableTiming);
            cudaEventCreateWithFlags(&evVh1[r],  cudaEventDisableTiming);
            cudaEventCreateWithFlags(&evGru[r],  cudaEventDisableTiming);
        }
        cudaFuncSetAttribute(mma_gemm_dual_kernel,
                             cudaFuncAttributeMaxDynamicSharedMemorySize, GEMM_SMEM);
        cudaFuncSetAttribute(mma_gemm_batch_kernel,
                             cudaFuncAttributeMaxDynamicSharedMemorySize, GEMM_SMEM);
        s_init = true;
    }

    // ---- fork prep branch onto sB: hv0 split + weight splits + batch GEMM ----
    cudaEventRecord(evFork, 0);
    cudaStreamWaitEvent(sB, evFork, 0);
    split_kernel<<<(N_NODES * H + 255) / 256, 256, 0, sB>>>(hv0, HvHi, HvLo, N_NODES * H);
    {
        const int total = 2 * (GH * GH) + 2 * (TH * GH) + 2 * (TH * H);
        prep_split_kernel<<<(total + 255) / 256, 256, 0, sB>>>(msg_w, w_ih, w_hh);
    }
    mma_gemm_batch_kernel<<<dim3(H / 128, TH / 128, 4), 256, GEMM_SMEM, sB>>>();
    cudaEventRecord(evPrep, sB);                 // gates round GEMMs (B1/B2 ready)
    cbcw_kernel<<<(2 * TH + 7) / 8, 256, 0, sB>>>(msg_w, msg_b, w_ih);
    cudaEventRecord(evCbcw, sB);                 // gru2 round-0 is on sB after this (in-order)

    // ---- main: CSR build ----
    init_kernel<<<(N_NODES + 255) / 256, 256>>>();
    deg_kernel<<<(N_EDGES + 255) / 256, 256>>>(dst, he);
    scan_kernel<<<1, 1024>>>();
    scatter_kernel<<<(N_EDGES + 255) / 256, 256>>>(src, dst);
    cudaEventRecord(evT0, 0);

    for (int r = 0; r < 2; r++) {
        const float* hv_cur = (r == 0) ? hv0 : (const float*)Hv1;
        float* hv_next = (r == 0) ? Hv1 : out;
        const __nv_bfloat16 *b1h = B1Hi + (size_t)r * 1536 * H, *b1l = B1Lo + (size_t)r * 1536 * H;
        const __nv_bfloat16 *b2h = B2Hi + (size_t)r * TH * H,   *b2l = B2Lo + (size_t)r * TH * H;
        const float* cb = Cb + r * TH;
        const float* cw = Cw + r * TH;
        const float* bi = b_ih + (size_t)r * TH;
        const float* bh = b_hh + (size_t)r * TH;

        // sA: taggr -> V GEMM (two M-halves)
        cudaStreamWaitEvent(sA, (r == 0) ? evT0 : evGru[0], 0);
        taggr_kernel<<<N_NODES, 64, 0, sA>>>(hv_cur);
        if (r == 0) cudaStreamWaitEvent(sA, evPrep, 0);
        mma_gemm_dual_kernel<<<dim3(6, Y_H0), 256, GEMM_SMEM, sA>>>(
            HvHi, HvLo, TbHi, TbLo, b1h, b1l, b2h, b2l, G1, V, 12, 0);
        cudaEventRecord(evVh0[r], sA);
        mma_gemm_dual_kernel<<<dim3(6, Y_H1), 256, GEMM_SMEM, sA>>>(
            HvHi, HvLo, TbHi, TbLo, b1h, b1l, b2h, b2l, G1, V, 12, Y_H0);
        cudaEventRecord(evVh1[r], sA);

        // main: G1 GEMM (two M-halves)
        if (r == 0) cudaStreamWaitEvent(0, evPrep, 0);
        else        cudaStreamWaitEvent(0, evGru[0], 0);
        mma_gemm_dual_kernel<<<dim3(12, Y_H0), 256, GEMM_SMEM>>>(
            HvHi, HvLo, TbHi, TbLo, b1h, b1l, b2h, b2l, G1, V, 0, 0);
        cudaEventRecord(evG1h0[r], 0);
        mma_gemm_dual_kernel<<<dim3(12, Y_H1), 256, GEMM_SMEM>>>(
            HvHi, HvLo, TbHi, TbLo, b1h, b1l, b2h, b2l, G1, V, 0, Y_H0);
        cudaEventRecord(evG1h1[r], 0);

        // sB: gru2 halves, pipelined against the second GEMM half
        cudaStreamWaitEvent(sB, evG1h0[r], 0);
        cudaStreamWaitEvent(sB, evVh0[r], 0);
        if (r == 0)
            gru2_kernel<true, false><<<ROWS_H0 / 4, 256, 0, sB>>>(
                hv_cur, hv_next, cb, cw, bi, bh, dest_w, ntype, gate_w, gate_b,
                0, ROWS_H0);
        else
            gru2_kernel<false, true><<<ROWS_H0 / 4, 256, 0, sB>>>(
                hv_cur, hv_next, cb, cw, bi, bh, dest_w, ntype, gate_w, gate_b,
                0, ROWS_H0);
        cudaStreamWaitEvent(sB, evG1h1[r], 0);
        cudaStreamWaitEvent(sB, evVh1[r], 0);
        if (r == 0)
            gru2_kernel<true, false><<<ROWS_H1 / 4, 256, 0, sB>>>(
                hv_cur, hv_next, cb, cw, bi, bh, dest_w, ntype, gate_w, gate_b,
                ROWS_H0, ROWS_H1);
        else
            gru2_kernel<false, true><<<ROWS_H1 / 4, 256, 0, sB>>>(
                hv_cur, hv_next, cb, cw, bi, bh, dest_w, ntype, gate_w, gate_b,
                ROWS_H0, ROWS_H1);
        cudaEventRecord(evGru[r], sB);
    }

    // ---- tail: dest logsoftmax on sA, embed chain on main ----
    cudaStreamWaitEvent(sA, evGru[1], 0);
    destreduce_kernel<<<1, 1024, 0, sA>>>();
    destwrite_kernel<<<(N_NODES - 1 + 255) / 256, 256, 0, sA>>>(out + OFF_DEST);
    cudaEventRecord(evD, sA);

    cudaStreamWaitEvent(0, evGru[1], 0);
    gembed_part_kernel<<<dim3(GH / 128, NT), 128>>>(tog_w);
    gembed_final_kernel<<<1, 512>>>(tog_b, out + OFF_GEMB);
    heads_kernel<<<3, 256>>>(out + OFF_GEMB, out, addn_w, addn_b,
                             nte, init_w, init_b, adde_w, adde_b, out);

    // join everything back to the main stream before capture ends
    cudaStreamWaitEvent(0, evD, 0);
}